// round 5
// baseline (speedup 1.0000x reference)
#include <cuda_runtime.h>
#include <math.h>

#define N_NODES 4096
#define FIN     256
#define NHEAD   4
#define FHID    64
#define FFIN    64
#define NPROJ   16
#define MAXD    128

// ---------------- scratch ----------------
__device__ int   g_cols[2][N_NODES][MAXD];
__device__ int   g_deg [2][N_NODES];
__device__ float g_Wh  [N_NODES][512];      // x @ Wcat   (cols: g*256 + h*64 + f)
__device__ float g_s1  [2][NHEAD][N_NODES];
__device__ float g_s2  [2][NHEAD][N_NODES];
__device__ float g_hcat[2][N_NODES][256];   // layer-1 outputs (head-concat)
__device__ float g_Wh2 [2][N_NODES][64];
__device__ float g_s1o [2][N_NODES];
__device__ float g_s2o [2][N_NODES];

// =====================================================================
// Phase 1 (heterogeneous): blocks [0,256) do GEMM1 + logit epilogue,
// blocks [256,1280) do dense-mask -> CSR (DRAM-bound, runs concurrently).
// =====================================================================
__global__ void phase1(const float* __restrict__ x,
                       const float* __restrict__ W1, const float* __restrict__ W2,
                       const float* __restrict__ a1, const float* __restrict__ a2,
                       const float* __restrict__ m0, const float* __restrict__ m1) {
    int bid = blockIdx.x;
    int tid = threadIdx.x;

    if (bid >= 256) {
        // ---------------- CSR build: one warp per row, float4 scan ----------------
        int w    = (bid - 256) * 8 + (tid >> 5);
        int lane = tid & 31;
        int g = w >> 12, r = w & 4095;
        const float4* mask = (const float4*)((g ? m1 : m0) + (size_t)r * N_NODES);
        int cnt = 0;
        for (int jb = 0; jb < 1024; jb += 32) {
            float4 v = mask[jb + lane];
            unsigned nib = (v.x > 0.f) | ((v.y > 0.f) << 1) | ((v.z > 0.f) << 2) | ((v.w > 0.f) << 3);
            int c4 = __popc(nib);
            int s = c4;
            #pragma unroll
            for (int off = 1; off < 32; off <<= 1) {
                int t = __shfl_up_sync(0xffffffffu, s, off);
                if (lane >= off) s += t;
            }
            int base = cnt + s - c4;
            int colbase = (jb + lane) * 4;
            int p = 0;
            if (nib & 1) { if (base + p < MAXD) g_cols[g][r][base + p] = colbase;     p++; }
            if (nib & 2) { if (base + p < MAXD) g_cols[g][r][base + p] = colbase + 1; p++; }
            if (nib & 4) { if (base + p < MAXD) g_cols[g][r][base + p] = colbase + 2; p++; }
            if (nib & 8) { if (base + p < MAXD) g_cols[g][r][base + p] = colbase + 3; }
            cnt += __shfl_sync(0xffffffffu, s, 31);
        }
        if (lane == 0) g_deg[g][r] = cnt < MAXD ? cnt : MAXD;
        return;
    }

    // ---------------- GEMM1: Wh = x @ Wcat, tile 128x64, + s1/s2 epilogue ----------
    __shared__ float As[16][132];
    __shared__ float Bs[16][64];
    int bx = bid & 31, by = bid >> 5;         // by in [0,8)
    int m0r = bx * 128, n0 = by * 64;
    int gsel = by >> 2, h = by & 3;
    const float* W  = gsel ? W2 : W1;         // [4,256,64]
    const float* av = (gsel ? a2 : a1) + h * 128;
    int tx = tid & 15, ty = tid >> 4;

    float acc[8][4] = {};
    for (int kb = 0; kb < FIN; kb += 16) {
        #pragma unroll
        for (int i = 0; i < 2; i++) {
            int e4 = i * 256 + tid;
            int m = e4 >> 2, k4 = e4 & 3;
            float4 v = *(const float4*)(x + (size_t)(m0r + m) * FIN + kb + k4 * 4);
            As[k4 * 4 + 0][m] = v.x; As[k4 * 4 + 1][m] = v.y;
            As[k4 * 4 + 2][m] = v.z; As[k4 * 4 + 3][m] = v.w;
        }
        {
            int k = tid >> 4, nf = (tid & 15) * 4;
            float4 bv = *(const float4*)(W + ((size_t)(h * FIN + kb + k)) * FHID + nf);
            *(float4*)&Bs[k][nf] = bv;
        }
        __syncthreads();
        #pragma unroll
        for (int kk = 0; kk < 16; kk++) {
            float a[8], b[4];
            #pragma unroll
            for (int r = 0; r < 8; r++) a[r] = As[kk][ty * 8 + r];
            #pragma unroll
            for (int c = 0; c < 4; c++) b[c] = Bs[kk][tx * 4 + c];
            #pragma unroll
            for (int r = 0; r < 8; r++)
                #pragma unroll
                for (int c = 0; c < 4; c++)
                    acc[r][c] += a[r] * b[c];
        }
        __syncthreads();
    }
    #pragma unroll
    for (int r = 0; r < 8; r++) {
        int m = m0r + ty * 8 + r;
        float4 v = make_float4(acc[r][0], acc[r][1], acc[r][2], acc[r][3]);
        *(float4*)&g_Wh[m][n0 + tx * 4] = v;
    }
    float a_s[4], a_d[4];
    #pragma unroll
    for (int c = 0; c < 4; c++) {
        a_s[c] = __ldg(av + tx * 4 + c);
        a_d[c] = __ldg(av + 64 + tx * 4 + c);
    }
    #pragma unroll
    for (int r = 0; r < 8; r++) {
        float s1 = 0.f, s2 = 0.f;
        #pragma unroll
        for (int c = 0; c < 4; c++) { s1 += acc[r][c] * a_s[c]; s2 += acc[r][c] * a_d[c]; }
        #pragma unroll
        for (int off = 1; off < 16; off <<= 1) {
            s1 += __shfl_xor_sync(0xffffffffu, s1, off);
            s2 += __shfl_xor_sync(0xffffffffu, s2, off);
        }
        if (tx == 0) {
            int m = m0r + ty * 8 + r;
            g_s1[gsel][h][m] = s1;
            g_s2[gsel][h][m] = s2;
        }
    }
}

// =====================================================================
// Layer-1 attention: one warp per (node, graph, head). Barrier-free.
// grid 4096 x 256 threads -> 8 warps/block = 1 node (2 g x 4 h).
// Register arrays only ever indexed by compile-time constants.
// =====================================================================
__global__ void attn_layer1() {
    int tid  = threadIdx.x;
    int lane = tid & 31;
    int w    = tid >> 5;        // 0..7
    int h    = w & 3;
    int g    = w >> 2;
    int i    = blockIdx.x;

    int d = g_deg[g][i];
    int   cr[4];
    float er[4];
    float s1v = g_s1[g][h][i];
    float m = -INFINITY;
    #pragma unroll
    for (int j = 0; j < 4; j++) {
        int k = lane + 32 * j;
        if (k < d) {
            int c = g_cols[g][i][k];
            cr[j] = c;
            float z = s1v + g_s2[g][h][c];
            z = z >= 0.f ? z : 0.2f * z;
            er[j] = z;
            m = fmaxf(m, z);
        } else { cr[j] = 0; er[j] = -INFINITY; }
    }
    #pragma unroll
    for (int off = 16; off; off >>= 1) m = fmaxf(m, __shfl_xor_sync(0xffffffffu, m, off));
    float sum = 0.f;
    #pragma unroll
    for (int j = 0; j < 4; j++) {
        int k = lane + 32 * j;
        float p = (k < d) ? __expf(er[j] - m) : 0.f;
        er[j] = p;
        sum += p;
    }
    #pragma unroll
    for (int off = 16; off; off >>= 1) sum += __shfl_xor_sync(0xffffffffu, sum, off);
    float inv = 1.f / sum;

    // gather: lane owns features (2*lane, 2*lane+1) of this head.
    // chunked broadcast: register index j is a compile-time constant.
    int colbase = g * 256 + h * 64 + 2 * lane;
    float ax = 0.f, ay = 0.f;
    #pragma unroll
    for (int j = 0; j < 4; j++) {
        int base = 32 * j;
        if (base >= d) break;
        int lim = d - base; if (lim > 32) lim = 32;
        int   cj = cr[j];
        float ej = er[j];
        for (int kk = 0; kk < lim; kk++) {
            int   c = __shfl_sync(0xffffffffu, cj, kk);
            float e = __shfl_sync(0xffffffffu, ej, kk);
            float2 v = *(const float2*)&g_Wh[c][colbase];
            ax += e * v.x;
            ay += e * v.y;
        }
    }
    ax *= inv; ay *= inv;
    float2 o;
    o.x = ax > 0.f ? ax : (__expf(ax) - 1.f);
    o.y = ay > 0.f ? ay : (__expf(ay) - 1.f);
    *(float2*)&g_hcat[g][i][h * 64 + 2 * lane] = o;
}

// =====================================================================
// GEMM2 (both graphs, one launch): Wh2_g = hcat_g @ Wo_g, tile 64x64,
// + s1o/s2o epilogue.  grid (64, 2), block 256, microtile 4x4.
// =====================================================================
__global__ void gemm2f(const float* __restrict__ Wo1, const float* __restrict__ Wo2,
                       const float* __restrict__ ao1, const float* __restrict__ ao2) {
    __shared__ float As[16][68];
    __shared__ float Bs[16][64];
    int g = blockIdx.y;
    int m0r = blockIdx.x * 64;
    const float* A  = &g_hcat[g][0][0];
    const float* B  = g ? Wo2 : Wo1;
    const float* ao = g ? ao2 : ao1;
    int tid = threadIdx.x;
    int tx = tid & 15, ty = tid >> 4;

    float acc[4][4] = {};
    for (int kb = 0; kb < 256; kb += 16) {
        {
            int m = tid >> 2, k4 = tid & 3;
            float4 v = *(const float4*)(A + (size_t)(m0r + m) * 256 + kb + k4 * 4);
            As[k4 * 4 + 0][m] = v.x; As[k4 * 4 + 1][m] = v.y;
            As[k4 * 4 + 2][m] = v.z; As[k4 * 4 + 3][m] = v.w;
        }
        {
            int k = tid >> 4, nf = (tid & 15) * 4;
            float4 bv = *(const float4*)(B + (size_t)(kb + k) * 64 + nf);
            *(float4*)&Bs[k][nf] = bv;
        }
        __syncthreads();
        #pragma unroll
        for (int kk = 0; kk < 16; kk++) {
            float a[4], b[4];
            #pragma unroll
            for (int r = 0; r < 4; r++) a[r] = As[kk][ty * 4 + r];
            #pragma unroll
            for (int c = 0; c < 4; c++) b[c] = Bs[kk][tx * 4 + c];
            #pragma unroll
            for (int r = 0; r < 4; r++)
                #pragma unroll
                for (int c = 0; c < 4; c++)
                    acc[r][c] += a[r] * b[c];
        }
        __syncthreads();
    }
    #pragma unroll
    for (int r = 0; r < 4; r++) {
        int m = m0r + ty * 4 + r;
        float4 v = make_float4(acc[r][0], acc[r][1], acc[r][2], acc[r][3]);
        *(float4*)&g_Wh2[g][m][tx * 4] = v;
    }
    float a_s[4], a_d[4];
    #pragma unroll
    for (int c = 0; c < 4; c++) {
        a_s[c] = __ldg(ao + tx * 4 + c);
        a_d[c] = __ldg(ao + 64 + tx * 4 + c);
    }
    #pragma unroll
    for (int r = 0; r < 4; r++) {
        float s1 = 0.f, s2 = 0.f;
        #pragma unroll
        for (int c = 0; c < 4; c++) { s1 += acc[r][c] * a_s[c]; s2 += acc[r][c] * a_d[c]; }
        #pragma unroll
        for (int off = 1; off < 16; off <<= 1) {
            s1 += __shfl_xor_sync(0xffffffffu, s1, off);
            s2 += __shfl_xor_sync(0xffffffffu, s2, off);
        }
        if (tx == 0) {
            int m = m0r + ty * 4 + r;
            g_s1o[g][m] = s1;
            g_s2o[g][m] = s2;
        }
    }
}

// =====================================================================
// Layer-2 attention + ELU + semantic fusion.
// One warp per (node, graph); 256-thread block handles 4 nodes.
// =====================================================================
__global__ void attn2_final(const float* __restrict__ Wp1, const float* __restrict__ bp1,
                            const float* __restrict__ Wp2, float* __restrict__ out) {
    int tid  = threadIdx.x;
    int lane = tid & 31;
    int w    = tid >> 5;        // 0..7
    int n    = w >> 1;          // node slot 0..3
    int g    = w & 1;
    int i    = blockIdx.x * 4 + n;

    __shared__ float se[4][2][64];
    __shared__ float tt[4][2][16];

    int d = g_deg[g][i];
    int   cr[4];
    float er[4];
    float s1v = g_s1o[g][i];
    float m = -INFINITY;
    #pragma unroll
    for (int j = 0; j < 4; j++) {
        int k = lane + 32 * j;
        if (k < d) {
            int c = g_cols[g][i][k];
            cr[j] = c;
            float z = s1v + g_s2o[g][c];
            z = z >= 0.f ? z : 0.2f * z;
            er[j] = z;
            m = fmaxf(m, z);
        } else { cr[j] = 0; er[j] = -INFINITY; }
    }
    #pragma unroll
    for (int off = 16; off; off >>= 1) m = fmaxf(m, __shfl_xor_sync(0xffffffffu, m, off));
    float sum = 0.f;
    #pragma unroll
    for (int j = 0; j < 4; j++) {
        int k = lane + 32 * j;
        float p = (k < d) ? __expf(er[j] - m) : 0.f;
        er[j] = p;
        sum += p;
    }
    #pragma unroll
    for (int off = 16; off; off >>= 1) sum += __shfl_xor_sync(0xffffffffu, sum, off);
    float inv = 1.f / sum;

    float ax = 0.f, ay = 0.f;
    #pragma unroll
    for (int j = 0; j < 4; j++) {
        int base = 32 * j;
        if (base >= d) break;
        int lim = d - base; if (lim > 32) lim = 32;
        int   cj = cr[j];
        float ej = er[j];
        for (int kk = 0; kk < lim; kk++) {
            int   c = __shfl_sync(0xffffffffu, cj, kk);
            float e = __shfl_sync(0xffffffffu, ej, kk);
            float2 v = *(const float2*)&g_Wh2[g][c][2 * lane];
            ax += e * v.x;
            ay += e * v.y;
        }
    }
    ax *= inv; ay *= inv;
    se[n][g][2 * lane]     = ax > 0.f ? ax : (__expf(ax) - 1.f);
    se[n][g][2 * lane + 1] = ay > 0.f ? ay : (__expf(ay) - 1.f);
    __syncthreads();

    // projection: 128 threads = 4 nodes x 2 g x 16 p
    if (tid < 128) {
        int pn = tid >> 5, pg = (tid >> 4) & 1, p = tid & 15;
        float s = __ldg(bp1 + p);
        #pragma unroll
        for (int f = 0; f < 64; f++) s += se[pn][pg][f] * __ldg(Wp1 + f * NPROJ + p);
        tt[pn][pg][p] = tanhf(s);
    }
    __syncthreads();

    // output: 256 threads = 4 nodes x 64 feats; each recomputes beta (smem, cheap)
    int on = tid >> 6, f = tid & 63;
    float w0 = 0.f, w1 = 0.f;
    #pragma unroll
    for (int p = 0; p < NPROJ; p++) {
        float wp = __ldg(Wp2 + p);
        w0 += tt[on][0][p] * wp;
        w1 += tt[on][1][p] * wp;
    }
    float mm = fmaxf(w0, w1);
    float b0 = __expf(w0 - mm), b1 = __expf(w1 - mm);
    float ib = 1.f / (b0 + b1);
    int oi = blockIdx.x * 4 + on;
    out[(size_t)oi * 64 + f] = (b0 * se[on][0][f] + b1 * se[on][1][f]) * ib;
}

// ---------------- launch ----------------
extern "C" void kernel_launch(void* const* d_in, const int* in_sizes, int n_in,
                              void* d_out, int out_size) {
    const float* x    = (const float*)d_in[0];
    const float* sadj = (const float*)d_in[1];
    const float* sadj2= (const float*)d_in[2];
    const float* W1   = (const float*)d_in[3];
    const float* a1   = (const float*)d_in[4];
    const float* Wo1  = (const float*)d_in[5];
    const float* ao1  = (const float*)d_in[6];
    const float* W2   = (const float*)d_in[7];
    const float* a2   = (const float*)d_in[8];
    const float* Wo2  = (const float*)d_in[9];
    const float* ao2  = (const float*)d_in[10];
    const float* Wp1  = (const float*)d_in[11];
    const float* bp1  = (const float*)d_in[12];
    const float* Wp2  = (const float*)d_in[13];
    float* out = (float*)d_out;

    phase1<<<1280, 256>>>(x, W1, W2, a1, a2, sadj, sadj2);
    attn_layer1<<<4096, 256>>>();
    gemm2f<<<dim3(64, 2), 256>>>(Wo1, Wo2, ao1, ao2);
    attn2_final<<<1024, 256>>>(Wp1, bp1, Wp2, out);
}

// round 6
// speedup vs baseline: 1.0813x; 1.0813x over previous
#include <cuda_runtime.h>
#include <math.h>

#define N_NODES 4096
#define FIN     256
#define NHEAD   4
#define FHID    64
#define FFIN    64
#define NPROJ   16
#define MAXD    128

// ---------------- scratch ----------------
__device__ int   g_cols[2][N_NODES][MAXD];
__device__ int   g_deg [2][N_NODES];
__device__ float g_Wh  [N_NODES][512];      // x @ Wcat   (cols: g*256 + h*64 + f)
__device__ float g_s1  [2][NHEAD][N_NODES];
__device__ float g_s2  [2][NHEAD][N_NODES];
__device__ float g_hcat[2][N_NODES][256];   // layer-1 outputs (head-concat)
__device__ float g_Wh2 [2][N_NODES][64];
__device__ float g_s1o [2][N_NODES];
__device__ float g_s2o [2][N_NODES];

// =====================================================================
// Phase 1 (heterogeneous): blocks [0,256) do GEMM1 + logit epilogue,
// blocks [256,1280) do dense-mask -> CSR (DRAM-bound, runs concurrently).
// =====================================================================
__global__ void phase1(const float* __restrict__ x,
                       const float* __restrict__ W1, const float* __restrict__ W2,
                       const float* __restrict__ a1, const float* __restrict__ a2,
                       const float* __restrict__ m0, const float* __restrict__ m1) {
    int bid = blockIdx.x;
    int tid = threadIdx.x;

    if (bid >= 256) {
        // ---------------- CSR build: one warp per row, float4 scan ----------------
        int w    = (bid - 256) * 8 + (tid >> 5);
        int lane = tid & 31;
        int g = w >> 12, r = w & 4095;
        const float4* mask = (const float4*)((g ? m1 : m0) + (size_t)r * N_NODES);
        int cnt = 0;
        for (int jb = 0; jb < 1024; jb += 32) {
            float4 v = mask[jb + lane];
            unsigned nib = (v.x > 0.f) | ((v.y > 0.f) << 1) | ((v.z > 0.f) << 2) | ((v.w > 0.f) << 3);
            int c4 = __popc(nib);
            int s = c4;
            #pragma unroll
            for (int off = 1; off < 32; off <<= 1) {
                int t = __shfl_up_sync(0xffffffffu, s, off);
                if (lane >= off) s += t;
            }
            int base = cnt + s - c4;
            int colbase = (jb + lane) * 4;
            int p = 0;
            if (nib & 1) { if (base + p < MAXD) g_cols[g][r][base + p] = colbase;     p++; }
            if (nib & 2) { if (base + p < MAXD) g_cols[g][r][base + p] = colbase + 1; p++; }
            if (nib & 4) { if (base + p < MAXD) g_cols[g][r][base + p] = colbase + 2; p++; }
            if (nib & 8) { if (base + p < MAXD) g_cols[g][r][base + p] = colbase + 3; }
            cnt += __shfl_sync(0xffffffffu, s, 31);
        }
        if (lane == 0) g_deg[g][r] = cnt < MAXD ? cnt : MAXD;
        return;
    }

    // ---------------- GEMM1: Wh = x @ Wcat, tile 128x64, + s1/s2 epilogue ----------
    __shared__ float As[16][132];
    __shared__ float Bs[16][64];
    int bx = bid & 31, by = bid >> 5;         // by in [0,8)
    int m0r = bx * 128, n0 = by * 64;
    int gsel = by >> 2, h = by & 3;
    const float* W  = gsel ? W2 : W1;         // [4,256,64]
    const float* av = (gsel ? a2 : a1) + h * 128;
    int tx = tid & 15, ty = tid >> 4;

    float acc[8][4] = {};
    for (int kb = 0; kb < FIN; kb += 16) {
        #pragma unroll
        for (int i = 0; i < 2; i++) {
            int e4 = i * 256 + tid;
            int m = e4 >> 2, k4 = e4 & 3;
            float4 v = *(const float4*)(x + (size_t)(m0r + m) * FIN + kb + k4 * 4);
            As[k4 * 4 + 0][m] = v.x; As[k4 * 4 + 1][m] = v.y;
            As[k4 * 4 + 2][m] = v.z; As[k4 * 4 + 3][m] = v.w;
        }
        {
            int k = tid >> 4, nf = (tid & 15) * 4;
            float4 bv = *(const float4*)(W + ((size_t)(h * FIN + kb + k)) * FHID + nf);
            *(float4*)&Bs[k][nf] = bv;
        }
        __syncthreads();
        #pragma unroll
        for (int kk = 0; kk < 16; kk++) {
            float a[8], b[4];
            #pragma unroll
            for (int r = 0; r < 8; r++) a[r] = As[kk][ty * 8 + r];
            #pragma unroll
            for (int c = 0; c < 4; c++) b[c] = Bs[kk][tx * 4 + c];
            #pragma unroll
            for (int r = 0; r < 8; r++)
                #pragma unroll
                for (int c = 0; c < 4; c++)
                    acc[r][c] += a[r] * b[c];
        }
        __syncthreads();
    }
    #pragma unroll
    for (int r = 0; r < 8; r++) {
        int m = m0r + ty * 8 + r;
        float4 v = make_float4(acc[r][0], acc[r][1], acc[r][2], acc[r][3]);
        *(float4*)&g_Wh[m][n0 + tx * 4] = v;
    }
    float a_s[4], a_d[4];
    #pragma unroll
    for (int c = 0; c < 4; c++) {
        a_s[c] = __ldg(av + tx * 4 + c);
        a_d[c] = __ldg(av + 64 + tx * 4 + c);
    }
    #pragma unroll
    for (int r = 0; r < 8; r++) {
        float s1 = 0.f, s2 = 0.f;
        #pragma unroll
        for (int c = 0; c < 4; c++) { s1 += acc[r][c] * a_s[c]; s2 += acc[r][c] * a_d[c]; }
        #pragma unroll
        for (int off = 1; off < 16; off <<= 1) {
            s1 += __shfl_xor_sync(0xffffffffu, s1, off);
            s2 += __shfl_xor_sync(0xffffffffu, s2, off);
        }
        if (tx == 0) {
            int m = m0r + ty * 8 + r;
            g_s1[gsel][h][m] = s1;
            g_s2[gsel][h][m] = s2;
        }
    }
}

// ---- MLP=4 gather helper: broadcast 4 (col,e) pairs, batch 4 loads ----
// row_base points at the fp32 table row stride `stride`; lane offset already applied.
__device__ __forceinline__ void gather4(const float* __restrict__ tab, int stride,
                                        int cj, float ej, int kk,
                                        float& ax, float& ay) {
    int   c0 = __shfl_sync(0xffffffffu, cj, kk);
    int   c1 = __shfl_sync(0xffffffffu, cj, kk + 1);
    int   c2 = __shfl_sync(0xffffffffu, cj, kk + 2);
    int   c3 = __shfl_sync(0xffffffffu, cj, kk + 3);
    float e0 = __shfl_sync(0xffffffffu, ej, kk);
    float e1 = __shfl_sync(0xffffffffu, ej, kk + 1);
    float e2 = __shfl_sync(0xffffffffu, ej, kk + 2);
    float e3 = __shfl_sync(0xffffffffu, ej, kk + 3);
    float2 v0 = *(const float2*)(tab + (size_t)c0 * stride);
    float2 v1 = *(const float2*)(tab + (size_t)c1 * stride);
    float2 v2 = *(const float2*)(tab + (size_t)c2 * stride);
    float2 v3 = *(const float2*)(tab + (size_t)c3 * stride);
    ax += e0 * v0.x + e1 * v1.x + e2 * v2.x + e3 * v3.x;
    ay += e0 * v0.y + e1 * v1.y + e2 * v2.y + e3 * v3.y;
}

// =====================================================================
// Layer-1 attention: one warp per (node, graph, head). Barrier-free.
// grid 4096 x 256 threads -> 8 warps/block = 1 node (2 g x 4 h).
// =====================================================================
__global__ void attn_layer1() {
    int tid  = threadIdx.x;
    int lane = tid & 31;
    int w    = tid >> 5;        // 0..7
    int h    = w & 3;
    int g    = w >> 2;
    int i    = blockIdx.x;

    int d = g_deg[g][i];
    int   cr[4];
    float er[4];
    float s1v = g_s1[g][h][i];
    float m = -INFINITY;
    #pragma unroll
    for (int j = 0; j < 4; j++) {
        int k = lane + 32 * j;
        if (k < d) {
            int c = g_cols[g][i][k];
            cr[j] = c;
            float z = s1v + g_s2[g][h][c];
            z = z >= 0.f ? z : 0.2f * z;
            er[j] = z;
            m = fmaxf(m, z);
        } else { cr[j] = 0; er[j] = -INFINITY; }
    }
    #pragma unroll
    for (int off = 16; off; off >>= 1) m = fmaxf(m, __shfl_xor_sync(0xffffffffu, m, off));
    float sum = 0.f;
    #pragma unroll
    for (int j = 0; j < 4; j++) {
        int k = lane + 32 * j;
        float p = (k < d) ? __expf(er[j] - m) : 0.f;
        er[j] = p;
        sum += p;
    }
    #pragma unroll
    for (int off = 16; off; off >>= 1) sum += __shfl_xor_sync(0xffffffffu, sum, off);
    float inv = 1.f / sum;

    // gather, MLP=4: lane owns features (2*lane, 2*lane+1) of this head
    const float* tab = &g_Wh[0][g * 256 + h * 64 + 2 * lane];
    float ax = 0.f, ay = 0.f;
    #pragma unroll
    for (int j = 0; j < 4; j++) {
        int lim = d - 32 * j;
        lim = lim < 0 ? 0 : (lim > 32 ? 32 : lim);
        int   cj = cr[j];
        float ej = er[j];
        int kk = 0;
        for (; kk + 4 <= lim; kk += 4)
            gather4(tab, 512, cj, ej, kk, ax, ay);
        for (; kk < lim; kk++) {
            int   c = __shfl_sync(0xffffffffu, cj, kk);
            float e = __shfl_sync(0xffffffffu, ej, kk);
            float2 v = *(const float2*)(tab + (size_t)c * 512);
            ax += e * v.x;
            ay += e * v.y;
        }
    }
    ax *= inv; ay *= inv;
    float2 o;
    o.x = ax > 0.f ? ax : (__expf(ax) - 1.f);
    o.y = ay > 0.f ? ay : (__expf(ay) - 1.f);
    *(float2*)&g_hcat[g][i][h * 64 + 2 * lane] = o;
}

// =====================================================================
// GEMM2 (both graphs, one launch): Wh2_g = hcat_g @ Wo_g, tile 64x64,
// + s1o/s2o epilogue.  grid (64, 2), block 256, microtile 4x4.
// =====================================================================
__global__ void gemm2f(const float* __restrict__ Wo1, const float* __restrict__ Wo2,
                       const float* __restrict__ ao1, const float* __restrict__ ao2) {
    __shared__ float As[16][68];
    __shared__ float Bs[16][64];
    int g = blockIdx.y;
    int m0r = blockIdx.x * 64;
    const float* A  = &g_hcat[g][0][0];
    const float* B  = g ? Wo2 : Wo1;
    const float* ao = g ? ao2 : ao1;
    int tid = threadIdx.x;
    int tx = tid & 15, ty = tid >> 4;

    float acc[4][4] = {};
    for (int kb = 0; kb < 256; kb += 16) {
        {
            int m = tid >> 2, k4 = tid & 3;
            float4 v = *(const float4*)(A + (size_t)(m0r + m) * 256 + kb + k4 * 4);
            As[k4 * 4 + 0][m] = v.x; As[k4 * 4 + 1][m] = v.y;
            As[k4 * 4 + 2][m] = v.z; As[k4 * 4 + 3][m] = v.w;
        }
        {
            int k = tid >> 4, nf = (tid & 15) * 4;
            float4 bv = *(const float4*)(B + (size_t)(kb + k) * 64 + nf);
            *(float4*)&Bs[k][nf] = bv;
        }
        __syncthreads();
        #pragma unroll
        for (int kk = 0; kk < 16; kk++) {
            float a[4], b[4];
            #pragma unroll
            for (int r = 0; r < 4; r++) a[r] = As[kk][ty * 4 + r];
            #pragma unroll
            for (int c = 0; c < 4; c++) b[c] = Bs[kk][tx * 4 + c];
            #pragma unroll
            for (int r = 0; r < 4; r++)
                #pragma unroll
                for (int c = 0; c < 4; c++)
                    acc[r][c] += a[r] * b[c];
        }
        __syncthreads();
    }
    #pragma unroll
    for (int r = 0; r < 4; r++) {
        int m = m0r + ty * 4 + r;
        float4 v = make_float4(acc[r][0], acc[r][1], acc[r][2], acc[r][3]);
        *(float4*)&g_Wh2[g][m][tx * 4] = v;
    }
    float a_s[4], a_d[4];
    #pragma unroll
    for (int c = 0; c < 4; c++) {
        a_s[c] = __ldg(ao + tx * 4 + c);
        a_d[c] = __ldg(ao + 64 + tx * 4 + c);
    }
    #pragma unroll
    for (int r = 0; r < 4; r++) {
        float s1 = 0.f, s2 = 0.f;
        #pragma unroll
        for (int c = 0; c < 4; c++) { s1 += acc[r][c] * a_s[c]; s2 += acc[r][c] * a_d[c]; }
        #pragma unroll
        for (int off = 1; off < 16; off <<= 1) {
            s1 += __shfl_xor_sync(0xffffffffu, s1, off);
            s2 += __shfl_xor_sync(0xffffffffu, s2, off);
        }
        if (tx == 0) {
            int m = m0r + ty * 4 + r;
            g_s1o[g][m] = s1;
            g_s2o[g][m] = s2;
        }
    }
}

// =====================================================================
// Layer-2 attention + ELU + semantic fusion.
// One warp per (node, graph); 256-thread block handles 4 nodes.
// =====================================================================
__global__ void attn2_final(const float* __restrict__ Wp1, const float* __restrict__ bp1,
                            const float* __restrict__ Wp2, float* __restrict__ out) {
    int tid  = threadIdx.x;
    int lane = tid & 31;
    int w    = tid >> 5;        // 0..7
    int n    = w >> 1;          // node slot 0..3
    int g    = w & 1;
    int i    = blockIdx.x * 4 + n;

    __shared__ float se[4][2][64];
    __shared__ float tt[4][2][16];

    int d = g_deg[g][i];
    int   cr[4];
    float er[4];
    float s1v = g_s1o[g][i];
    float m = -INFINITY;
    #pragma unroll
    for (int j = 0; j < 4; j++) {
        int k = lane + 32 * j;
        if (k < d) {
            int c = g_cols[g][i][k];
            cr[j] = c;
            float z = s1v + g_s2o[g][c];
            z = z >= 0.f ? z : 0.2f * z;
            er[j] = z;
            m = fmaxf(m, z);
        } else { cr[j] = 0; er[j] = -INFINITY; }
    }
    #pragma unroll
    for (int off = 16; off; off >>= 1) m = fmaxf(m, __shfl_xor_sync(0xffffffffu, m, off));
    float sum = 0.f;
    #pragma unroll
    for (int j = 0; j < 4; j++) {
        int k = lane + 32 * j;
        float p = (k < d) ? __expf(er[j] - m) : 0.f;
        er[j] = p;
        sum += p;
    }
    #pragma unroll
    for (int off = 16; off; off >>= 1) sum += __shfl_xor_sync(0xffffffffu, sum, off);
    float inv = 1.f / sum;

    const float* tab = &g_Wh2[g][0][2 * lane];
    float ax = 0.f, ay = 0.f;
    #pragma unroll
    for (int j = 0; j < 4; j++) {
        int lim = d - 32 * j;
        lim = lim < 0 ? 0 : (lim > 32 ? 32 : lim);
        int   cj = cr[j];
        float ej = er[j];
        int kk = 0;
        for (; kk + 4 <= lim; kk += 4)
            gather4(tab, 64, cj, ej, kk, ax, ay);
        for (; kk < lim; kk++) {
            int   c = __shfl_sync(0xffffffffu, cj, kk);
            float e = __shfl_sync(0xffffffffu, ej, kk);
            float2 v = *(const float2*)(tab + (size_t)c * 64);
            ax += e * v.x;
            ay += e * v.y;
        }
    }
    ax *= inv; ay *= inv;
    se[n][g][2 * lane]     = ax > 0.f ? ax : (__expf(ax) - 1.f);
    se[n][g][2 * lane + 1] = ay > 0.f ? ay : (__expf(ay) - 1.f);
    __syncthreads();

    // projection: 128 threads = 4 nodes x 2 g x 16 p
    if (tid < 128) {
        int pn = tid >> 5, pg = (tid >> 4) & 1, p = tid & 15;
        float s = __ldg(bp1 + p);
        #pragma unroll
        for (int f = 0; f < 64; f++) s += se[pn][pg][f] * __ldg(Wp1 + f * NPROJ + p);
        tt[pn][pg][p] = tanhf(s);
    }
    __syncthreads();

    // output: 256 threads = 4 nodes x 64 feats; each recomputes beta (smem, cheap)
    int on = tid >> 6, f = tid & 63;
    float w0 = 0.f, w1 = 0.f;
    #pragma unroll
    for (int p = 0; p < NPROJ; p++) {
        float wp = __ldg(Wp2 + p);
        w0 += tt[on][0][p] * wp;
        w1 += tt[on][1][p] * wp;
    }
    float mm = fmaxf(w0, w1);
    float b0 = __expf(w0 - mm), b1 = __expf(w1 - mm);
    float ib = 1.f / (b0 + b1);
    int oi = blockIdx.x * 4 + on;
    out[(size_t)oi * 64 + f] = (b0 * se[on][0][f] + b1 * se[on][1][f]) * ib;
}

// ---------------- launch ----------------
extern "C" void kernel_launch(void* const* d_in, const int* in_sizes, int n_in,
                              void* d_out, int out_size) {
    const float* x    = (const float*)d_in[0];
    const float* sadj = (const float*)d_in[1];
    const float* sadj2= (const float*)d_in[2];
    const float* W1   = (const float*)d_in[3];
    const float* a1   = (const float*)d_in[4];
    const float* Wo1  = (const float*)d_in[5];
    const float* ao1  = (const float*)d_in[6];
    const float* W2   = (const float*)d_in[7];
    const float* a2   = (const float*)d_in[8];
    const float* Wo2  = (const float*)d_in[9];
    const float* ao2  = (const float*)d_in[10];
    const float* Wp1  = (const float*)d_in[11];
    const float* bp1  = (const float*)d_in[12];
    const float* Wp2  = (const float*)d_in[13];
    float* out = (float*)d_out;

    phase1<<<1280, 256>>>(x, W1, W2, a1, a2, sadj, sadj2);
    attn_layer1<<<4096, 256>>>();
    gemm2f<<<dim3(64, 2), 256>>>(Wo1, Wo2, ao1, ao2);
    attn2_final<<<1024, 256>>>(Wp1, bp1, Wp2, out);
}

// round 7
// speedup vs baseline: 1.1017x; 1.0189x over previous
#include <cuda_runtime.h>
#include <math.h>

#define N_NODES 4096
#define FIN     256
#define NHEAD   4
#define FHID    64
#define FFIN    64
#define NPROJ   16
#define MAXD    128

// ---------------- scratch ----------------
__device__ int   g_cols[2][N_NODES][MAXD];
__device__ int   g_deg [2][N_NODES];
__device__ float g_Wh  [N_NODES][512];      // x @ Wcat   (cols: g*256 + h*64 + f)
__device__ float g_s1t [2][N_NODES][4];     // layer-1 src logits, 4 heads packed
__device__ float g_s2t [2][N_NODES][4];     // layer-1 dst logits, 4 heads packed
__device__ float g_hcat[2][N_NODES][256];   // layer-1 outputs (head-concat)
__device__ float g_Wh2 [2][N_NODES][64];
__device__ float g_s1o [2][N_NODES];
__device__ float g_s2o [2][N_NODES];

__device__ __forceinline__ float lkexp(float z) {
    z = z >= 0.f ? z : 0.2f * z;
    return __expf(z);
}
__device__ __forceinline__ float elu1(float v) {
    return v > 0.f ? v : (__expf(v) - 1.f);
}

// =====================================================================
// Phase 1 (heterogeneous): blocks [0,256) do GEMM1 + logit epilogue,
// blocks [256,1280) do dense-mask -> CSR (DRAM-bound, runs concurrently).
// =====================================================================
__global__ void phase1(const float* __restrict__ x,
                       const float* __restrict__ W1, const float* __restrict__ W2,
                       const float* __restrict__ a1, const float* __restrict__ a2,
                       const float* __restrict__ m0, const float* __restrict__ m1) {
    int bid = blockIdx.x;
    int tid = threadIdx.x;

    if (bid >= 256) {
        // ---------------- CSR build: one warp per row, float4 scan ----------------
        int w    = (bid - 256) * 8 + (tid >> 5);
        int lane = tid & 31;
        int g = w >> 12, r = w & 4095;
        const float4* mask = (const float4*)((g ? m1 : m0) + (size_t)r * N_NODES);
        int cnt = 0;
        for (int jb = 0; jb < 1024; jb += 32) {
            float4 v = mask[jb + lane];
            unsigned nib = (v.x > 0.f) | ((v.y > 0.f) << 1) | ((v.z > 0.f) << 2) | ((v.w > 0.f) << 3);
            int c4 = __popc(nib);
            int s = c4;
            #pragma unroll
            for (int off = 1; off < 32; off <<= 1) {
                int t = __shfl_up_sync(0xffffffffu, s, off);
                if (lane >= off) s += t;
            }
            int base = cnt + s - c4;
            int colbase = (jb + lane) * 4;
            int p = 0;
            if (nib & 1) { if (base + p < MAXD) g_cols[g][r][base + p] = colbase;     p++; }
            if (nib & 2) { if (base + p < MAXD) g_cols[g][r][base + p] = colbase + 1; p++; }
            if (nib & 4) { if (base + p < MAXD) g_cols[g][r][base + p] = colbase + 2; p++; }
            if (nib & 8) { if (base + p < MAXD) g_cols[g][r][base + p] = colbase + 3; }
            cnt += __shfl_sync(0xffffffffu, s, 31);
        }
        if (lane == 0) g_deg[g][r] = cnt < MAXD ? cnt : MAXD;
        return;
    }

    // ---------------- GEMM1: Wh = x @ Wcat, tile 128x64, + s1/s2 epilogue ----------
    __shared__ float As[16][132];
    __shared__ float Bs[16][64];
    int bx = bid & 31, by = bid >> 5;         // by in [0,8)
    int m0r = bx * 128, n0 = by * 64;
    int gsel = by >> 2, h = by & 3;
    const float* W  = gsel ? W2 : W1;         // [4,256,64]
    const float* av = (gsel ? a2 : a1) + h * 128;
    int tx = tid & 15, ty = tid >> 4;

    float acc[8][4] = {};
    for (int kb = 0; kb < FIN; kb += 16) {
        #pragma unroll
        for (int i = 0; i < 2; i++) {
            int e4 = i * 256 + tid;
            int m = e4 >> 2, k4 = e4 & 3;
            float4 v = *(const float4*)(x + (size_t)(m0r + m) * FIN + kb + k4 * 4);
            As[k4 * 4 + 0][m] = v.x; As[k4 * 4 + 1][m] = v.y;
            As[k4 * 4 + 2][m] = v.z; As[k4 * 4 + 3][m] = v.w;
        }
        {
            int k = tid >> 4, nf = (tid & 15) * 4;
            float4 bv = *(const float4*)(W + ((size_t)(h * FIN + kb + k)) * FHID + nf);
            *(float4*)&Bs[k][nf] = bv;
        }
        __syncthreads();
        #pragma unroll
        for (int kk = 0; kk < 16; kk++) {
            float a[8], b[4];
            #pragma unroll
            for (int r = 0; r < 8; r++) a[r] = As[kk][ty * 8 + r];
            #pragma unroll
            for (int c = 0; c < 4; c++) b[c] = Bs[kk][tx * 4 + c];
            #pragma unroll
            for (int r = 0; r < 8; r++)
                #pragma unroll
                for (int c = 0; c < 4; c++)
                    acc[r][c] += a[r] * b[c];
        }
        __syncthreads();
    }
    #pragma unroll
    for (int r = 0; r < 8; r++) {
        int m = m0r + ty * 8 + r;
        float4 v = make_float4(acc[r][0], acc[r][1], acc[r][2], acc[r][3]);
        *(float4*)&g_Wh[m][n0 + tx * 4] = v;
    }
    float a_s[4], a_d[4];
    #pragma unroll
    for (int c = 0; c < 4; c++) {
        a_s[c] = __ldg(av + tx * 4 + c);
        a_d[c] = __ldg(av + 64 + tx * 4 + c);
    }
    #pragma unroll
    for (int r = 0; r < 8; r++) {
        float s1 = 0.f, s2 = 0.f;
        #pragma unroll
        for (int c = 0; c < 4; c++) { s1 += acc[r][c] * a_s[c]; s2 += acc[r][c] * a_d[c]; }
        #pragma unroll
        for (int off = 1; off < 16; off <<= 1) {
            s1 += __shfl_xor_sync(0xffffffffu, s1, off);
            s2 += __shfl_xor_sync(0xffffffffu, s2, off);
        }
        if (tx == 0) {
            int m = m0r + ty * 8 + r;
            g_s1t[gsel][m][h] = s1;
            g_s2t[gsel][m][h] = s2;
        }
    }
}

// ---- 4-head gather chunk (attn1): broadcast (c, e0..e3), 2 edges per step,
//      8 independent LDG.64 in flight. tab already offset by g*256 + 2*lane.
__device__ __forceinline__ void gat_chunk1(const float* __restrict__ tab, int lim,
                                           int cj, float4 ej,
                                           float& ax0, float& ay0, float& ax1, float& ay1,
                                           float& ax2, float& ay2, float& ax3, float& ay3) {
    int kk = 0;
    for (; kk + 2 <= lim; kk += 2) {
        int   ca  = __shfl_sync(0xffffffffu, cj, kk);
        int   cb  = __shfl_sync(0xffffffffu, cj, kk + 1);
        float ea0 = __shfl_sync(0xffffffffu, ej.x, kk);
        float ea1 = __shfl_sync(0xffffffffu, ej.y, kk);
        float ea2 = __shfl_sync(0xffffffffu, ej.z, kk);
        float ea3 = __shfl_sync(0xffffffffu, ej.w, kk);
        float eb0 = __shfl_sync(0xffffffffu, ej.x, kk + 1);
        float eb1 = __shfl_sync(0xffffffffu, ej.y, kk + 1);
        float eb2 = __shfl_sync(0xffffffffu, ej.z, kk + 1);
        float eb3 = __shfl_sync(0xffffffffu, ej.w, kk + 1);
        const float* ra = tab + (size_t)ca * 512;
        const float* rb = tab + (size_t)cb * 512;
        float2 va0 = *(const float2*)(ra);
        float2 va1 = *(const float2*)(ra + 64);
        float2 va2 = *(const float2*)(ra + 128);
        float2 va3 = *(const float2*)(ra + 192);
        float2 vb0 = *(const float2*)(rb);
        float2 vb1 = *(const float2*)(rb + 64);
        float2 vb2 = *(const float2*)(rb + 128);
        float2 vb3 = *(const float2*)(rb + 192);
        ax0 += ea0 * va0.x + eb0 * vb0.x;  ay0 += ea0 * va0.y + eb0 * vb0.y;
        ax1 += ea1 * va1.x + eb1 * vb1.x;  ay1 += ea1 * va1.y + eb1 * vb1.y;
        ax2 += ea2 * va2.x + eb2 * vb2.x;  ay2 += ea2 * va2.y + eb2 * vb2.y;
        ax3 += ea3 * va3.x + eb3 * vb3.x;  ay3 += ea3 * va3.y + eb3 * vb3.y;
    }
    if (kk < lim) {
        int   ca  = __shfl_sync(0xffffffffu, cj, kk);
        float ea0 = __shfl_sync(0xffffffffu, ej.x, kk);
        float ea1 = __shfl_sync(0xffffffffu, ej.y, kk);
        float ea2 = __shfl_sync(0xffffffffu, ej.z, kk);
        float ea3 = __shfl_sync(0xffffffffu, ej.w, kk);
        const float* ra = tab + (size_t)ca * 512;
        float2 va0 = *(const float2*)(ra);
        float2 va1 = *(const float2*)(ra + 64);
        float2 va2 = *(const float2*)(ra + 128);
        float2 va3 = *(const float2*)(ra + 192);
        ax0 += ea0 * va0.x;  ay0 += ea0 * va0.y;
        ax1 += ea1 * va1.x;  ay1 += ea1 * va1.y;
        ax2 += ea2 * va2.x;  ay2 += ea2 * va2.y;
        ax3 += ea3 * va3.x;  ay3 += ea3 * va3.y;
    }
}

// =====================================================================
// Layer-1 attention: ONE warp per (node, graph), all 4 heads together.
// grid 1024 x 256 -> 8 warps = 4 nodes x 2 graphs. No barriers.
// =====================================================================
__global__ void attn_layer1() {
    int tid  = threadIdx.x;
    int lane = tid & 31;
    int w    = tid >> 5;
    int n    = w >> 1;
    int g    = w & 1;
    int i    = blockIdx.x * 4 + n;

    int d = g_deg[g][i];
    float4 s1 = *(const float4*)&g_s1t[g][i][0];

    int c0 = 0, c1 = 0;
    float4 e0 = make_float4(0.f, 0.f, 0.f, 0.f);
    float4 e1 = make_float4(0.f, 0.f, 0.f, 0.f);
    if (lane < d) {
        c0 = g_cols[g][i][lane];
        float4 s2 = *(const float4*)&g_s2t[g][c0][0];
        e0.x = lkexp(s1.x + s2.x);  e0.y = lkexp(s1.y + s2.y);
        e0.z = lkexp(s1.z + s2.z);  e0.w = lkexp(s1.w + s2.w);
    }
    if (lane + 32 < d) {
        c1 = g_cols[g][i][lane + 32];
        float4 s2 = *(const float4*)&g_s2t[g][c1][0];
        e1.x = lkexp(s1.x + s2.x);  e1.y = lkexp(s1.y + s2.y);
        e1.z = lkexp(s1.z + s2.z);  e1.w = lkexp(s1.w + s2.w);
    }
    float sx = e0.x + e1.x, sy = e0.y + e1.y, sz = e0.z + e1.z, sw = e0.w + e1.w;
    #pragma unroll
    for (int off = 16; off; off >>= 1) {
        sx += __shfl_xor_sync(0xffffffffu, sx, off);
        sy += __shfl_xor_sync(0xffffffffu, sy, off);
        sz += __shfl_xor_sync(0xffffffffu, sz, off);
        sw += __shfl_xor_sync(0xffffffffu, sw, off);
    }
    float ix = 1.f / sx, iy = 1.f / sy, iz = 1.f / sz, iw = 1.f / sw;

    const float* tab = &g_Wh[0][g * 256 + 2 * lane];
    float ax0 = 0.f, ay0 = 0.f, ax1 = 0.f, ay1 = 0.f;
    float ax2 = 0.f, ay2 = 0.f, ax3 = 0.f, ay3 = 0.f;
    int lim0 = d < 32 ? d : 32;
    int lim1 = d - 32; lim1 = lim1 < 0 ? 0 : lim1;
    gat_chunk1(tab, lim0, c0, e0, ax0, ay0, ax1, ay1, ax2, ay2, ax3, ay3);
    gat_chunk1(tab, lim1, c1, e1, ax0, ay0, ax1, ay1, ax2, ay2, ax3, ay3);

    float* orow = &g_hcat[g][i][2 * lane];
    float2 o;
    o.x = elu1(ax0 * ix);  o.y = elu1(ay0 * ix);  *(float2*)(orow)       = o;
    o.x = elu1(ax1 * iy);  o.y = elu1(ay1 * iy);  *(float2*)(orow + 64)  = o;
    o.x = elu1(ax2 * iz);  o.y = elu1(ay2 * iz);  *(float2*)(orow + 128) = o;
    o.x = elu1(ax3 * iw);  o.y = elu1(ay3 * iw);  *(float2*)(orow + 192) = o;
}

// =====================================================================
// GEMM2 (both graphs, one launch): Wh2_g = hcat_g @ Wo_g, tile 64x64,
// + s1o/s2o epilogue.  grid (64, 2), block 256, microtile 4x4.
// =====================================================================
__global__ void gemm2f(const float* __restrict__ Wo1, const float* __restrict__ Wo2,
                       const float* __restrict__ ao1, const float* __restrict__ ao2) {
    __shared__ float As[16][68];
    __shared__ float Bs[16][64];
    int g = blockIdx.y;
    int m0r = blockIdx.x * 64;
    const float* A  = &g_hcat[g][0][0];
    const float* B  = g ? Wo2 : Wo1;
    const float* ao = g ? ao2 : ao1;
    int tid = threadIdx.x;
    int tx = tid & 15, ty = tid >> 4;

    float acc[4][4] = {};
    for (int kb = 0; kb < 256; kb += 16) {
        {
            int m = tid >> 2, k4 = tid & 3;
            float4 v = *(const float4*)(A + (size_t)(m0r + m) * 256 + kb + k4 * 4);
            As[k4 * 4 + 0][m] = v.x; As[k4 * 4 + 1][m] = v.y;
            As[k4 * 4 + 2][m] = v.z; As[k4 * 4 + 3][m] = v.w;
        }
        {
            int k = tid >> 4, nf = (tid & 15) * 4;
            float4 bv = *(const float4*)(B + (size_t)(kb + k) * 64 + nf);
            *(float4*)&Bs[k][nf] = bv;
        }
        __syncthreads();
        #pragma unroll
        for (int kk = 0; kk < 16; kk++) {
            float a[4], b[4];
            #pragma unroll
            for (int r = 0; r < 4; r++) a[r] = As[kk][ty * 4 + r];
            #pragma unroll
            for (int c = 0; c < 4; c++) b[c] = Bs[kk][tx * 4 + c];
            #pragma unroll
            for (int r = 0; r < 4; r++)
                #pragma unroll
                for (int c = 0; c < 4; c++)
                    acc[r][c] += a[r] * b[c];
        }
        __syncthreads();
    }
    #pragma unroll
    for (int r = 0; r < 4; r++) {
        int m = m0r + ty * 4 + r;
        float4 v = make_float4(acc[r][0], acc[r][1], acc[r][2], acc[r][3]);
        *(float4*)&g_Wh2[g][m][tx * 4] = v;
    }
    float a_s[4], a_d[4];
    #pragma unroll
    for (int c = 0; c < 4; c++) {
        a_s[c] = __ldg(ao + tx * 4 + c);
        a_d[c] = __ldg(ao + 64 + tx * 4 + c);
    }
    #pragma unroll
    for (int r = 0; r < 4; r++) {
        float s1 = 0.f, s2 = 0.f;
        #pragma unroll
        for (int c = 0; c < 4; c++) { s1 += acc[r][c] * a_s[c]; s2 += acc[r][c] * a_d[c]; }
        #pragma unroll
        for (int off = 1; off < 16; off <<= 1) {
            s1 += __shfl_xor_sync(0xffffffffu, s1, off);
            s2 += __shfl_xor_sync(0xffffffffu, s2, off);
        }
        if (tx == 0) {
            int m = m0r + ty * 4 + r;
            g_s1o[g][m] = s1;
            g_s2o[g][m] = s2;
        }
    }
}

// ---- scalar gather chunk (attn2), MLP=4, stride 64 floats ----
__device__ __forceinline__ void gat_chunk2(const float* __restrict__ tab, int lim,
                                           int cj, float ej, float& ax, float& ay) {
    int kk = 0;
    for (; kk + 4 <= lim; kk += 4) {
        int   c0 = __shfl_sync(0xffffffffu, cj, kk);
        int   c1 = __shfl_sync(0xffffffffu, cj, kk + 1);
        int   c2 = __shfl_sync(0xffffffffu, cj, kk + 2);
        int   c3 = __shfl_sync(0xffffffffu, cj, kk + 3);
        float e0 = __shfl_sync(0xffffffffu, ej, kk);
        float e1 = __shfl_sync(0xffffffffu, ej, kk + 1);
        float e2 = __shfl_sync(0xffffffffu, ej, kk + 2);
        float e3 = __shfl_sync(0xffffffffu, ej, kk + 3);
        float2 v0 = *(const float2*)(tab + (size_t)c0 * 64);
        float2 v1 = *(const float2*)(tab + (size_t)c1 * 64);
        float2 v2 = *(const float2*)(tab + (size_t)c2 * 64);
        float2 v3 = *(const float2*)(tab + (size_t)c3 * 64);
        ax += e0 * v0.x + e1 * v1.x + e2 * v2.x + e3 * v3.x;
        ay += e0 * v0.y + e1 * v1.y + e2 * v2.y + e3 * v3.y;
    }
    for (; kk < lim; kk++) {
        int   c = __shfl_sync(0xffffffffu, cj, kk);
        float e = __shfl_sync(0xffffffffu, ej, kk);
        float2 v = *(const float2*)(tab + (size_t)c * 64);
        ax += e * v.x;
        ay += e * v.y;
    }
}

// =====================================================================
// Layer-2 attention + ELU + semantic fusion.
// One warp per (node, graph); 256-thread block handles 4 nodes.
// =====================================================================
__global__ void attn2_final(const float* __restrict__ Wp1, const float* __restrict__ bp1,
                            const float* __restrict__ Wp2, float* __restrict__ out) {
    int tid  = threadIdx.x;
    int lane = tid & 31;
    int w    = tid >> 5;        // 0..7
    int n    = w >> 1;          // node slot 0..3
    int g    = w & 1;
    int i    = blockIdx.x * 4 + n;

    __shared__ float se[4][2][64];
    __shared__ float tt[4][2][16];

    int d = g_deg[g][i];
    float s1v = g_s1o[g][i];
    int c0 = 0, c1 = 0;
    float e0 = 0.f, e1 = 0.f;
    if (lane < d) {
        c0 = g_cols[g][i][lane];
        e0 = lkexp(s1v + g_s2o[g][c0]);
    }
    if (lane + 32 < d) {
        c1 = g_cols[g][i][lane + 32];
        e1 = lkexp(s1v + g_s2o[g][c1]);
    }
    float sum = e0 + e1;
    #pragma unroll
    for (int off = 16; off; off >>= 1) sum += __shfl_xor_sync(0xffffffffu, sum, off);
    float inv = 1.f / sum;

    const float* tab = &g_Wh2[g][0][2 * lane];
    float ax = 0.f, ay = 0.f;
    int lim0 = d < 32 ? d : 32;
    int lim1 = d - 32; lim1 = lim1 < 0 ? 0 : lim1;
    gat_chunk2(tab, lim0, c0, e0, ax, ay);
    gat_chunk2(tab, lim1, c1, e1, ax, ay);

    ax *= inv; ay *= inv;
    se[n][g][2 * lane]     = elu1(ax);
    se[n][g][2 * lane + 1] = elu1(ay);
    __syncthreads();

    // projection: 128 threads = 4 nodes x 2 g x 16 p
    if (tid < 128) {
        int pn = tid >> 5, pg = (tid >> 4) & 1, p = tid & 15;
        float s = __ldg(bp1 + p);
        #pragma unroll
        for (int f = 0; f < 64; f++) s += se[pn][pg][f] * __ldg(Wp1 + f * NPROJ + p);
        tt[pn][pg][p] = tanhf(s);
    }
    __syncthreads();

    // output: 256 threads = 4 nodes x 64 feats; each recomputes beta (smem, cheap)
    int on = tid >> 6, f = tid & 63;
    float w0 = 0.f, w1 = 0.f;
    #pragma unroll
    for (int p = 0; p < NPROJ; p++) {
        float wp = __ldg(Wp2 + p);
        w0 += tt[on][0][p] * wp;
        w1 += tt[on][1][p] * wp;
    }
    float mm = fmaxf(w0, w1);
    float b0 = __expf(w0 - mm), b1 = __expf(w1 - mm);
    float ib = 1.f / (b0 + b1);
    int oi = blockIdx.x * 4 + on;
    out[(size_t)oi * 64 + f] = (b0 * se[on][0][f] + b1 * se[on][1][f]) * ib;
}

// ---------------- launch ----------------
extern "C" void kernel_launch(void* const* d_in, const int* in_sizes, int n_in,
                              void* d_out, int out_size) {
    const float* x    = (const float*)d_in[0];
    const float* sadj = (const float*)d_in[1];
    const float* sadj2= (const float*)d_in[2];
    const float* W1   = (const float*)d_in[3];
    const float* a1   = (const float*)d_in[4];
    const float* Wo1  = (const float*)d_in[5];
    const float* ao1  = (const float*)d_in[6];
    const float* W2   = (const float*)d_in[7];
    const float* a2   = (const float*)d_in[8];
    const float* Wo2  = (const float*)d_in[9];
    const float* ao2  = (const float*)d_in[10];
    const float* Wp1  = (const float*)d_in[11];
    const float* bp1  = (const float*)d_in[12];
    const float* Wp2  = (const float*)d_in[13];
    float* out = (float*)d_out;

    phase1<<<1280, 256>>>(x, W1, W2, a1, a2, sadj, sadj2);
    attn_layer1<<<1024, 256>>>();
    gemm2f<<<dim3(64, 2), 256>>>(Wo1, Wo2, ao1, ao2);
    attn2_final<<<1024, 256>>>(Wp1, bp1, Wp2, out);
}

// round 8
// speedup vs baseline: 1.1580x; 1.0511x over previous
#include <cuda_runtime.h>
#include <math.h>

#define N_NODES 4096
#define FIN     256
#define NHEAD   4
#define FHID    64
#define FFIN    64
#define NPROJ   16
#define MAXD    128

// ---------------- scratch ----------------
__device__ int   g_cols[2][N_NODES][MAXD];
__device__ int   g_deg [2][N_NODES];
__device__ float g_Wh  [N_NODES][512];      // x @ Wcat   (cols: g*256 + h*64 + f)
__device__ float g_s1t [2][N_NODES][4];     // layer-1 src logits, 4 heads packed
__device__ float g_s2t [2][N_NODES][4];     // layer-1 dst logits, 4 heads packed
__device__ float g_hcat[2][N_NODES][256];   // layer-1 outputs (head-concat)
__device__ float g_Wh2 [2][N_NODES][64];
__device__ float g_s1o [2][N_NODES];
__device__ float g_s2o [2][N_NODES];

__device__ __forceinline__ float lkexp(float z) {
    z = z >= 0.f ? z : 0.2f * z;
    return __expf(z);
}
__device__ __forceinline__ float elu1(float v) {
    return v > 0.f ? v : (__expf(v) - 1.f);
}

// =====================================================================
// CSR build (standalone, low regs, MLP=4): one warp per (graph,row).
// 1024 blocks x 256 threads = 8192 warps.
// =====================================================================
__device__ __forceinline__ void place_bits(unsigned nb, int cb, int& pos, int* __restrict__ row) {
    while (nb) {
        int b = __ffs(nb) - 1;
        nb &= nb - 1;
        if (pos < MAXD) row[pos] = cb + b;
        pos++;
    }
}

__global__ void csr_build(const float* __restrict__ m0, const float* __restrict__ m1) {
    int tid  = threadIdx.x;
    int w    = blockIdx.x * 8 + (tid >> 5);
    int lane = tid & 31;
    int g = w >> 12, r = w & 4095;
    const float4* mask = (const float4*)((g ? m1 : m0) + (size_t)r * N_NODES);
    int* row = &g_cols[g][r][0];
    int cnt = 0;
    for (int jb = 0; jb < 1024; jb += 128) {
        // 4 independent 16B loads (MLP=4)
        float4 v0 = mask[jb + lane];
        float4 v1 = mask[jb + 32 + lane];
        float4 v2 = mask[jb + 64 + lane];
        float4 v3 = mask[jb + 96 + lane];
        unsigned n0 = (v0.x > 0.f) | ((v0.y > 0.f) << 1) | ((v0.z > 0.f) << 2) | ((v0.w > 0.f) << 3);
        unsigned n1 = (v1.x > 0.f) | ((v1.y > 0.f) << 1) | ((v1.z > 0.f) << 2) | ((v1.w > 0.f) << 3);
        unsigned n2 = (v2.x > 0.f) | ((v2.y > 0.f) << 1) | ((v2.z > 0.f) << 2) | ((v2.w > 0.f) << 3);
        unsigned n3 = (v3.x > 0.f) | ((v3.y > 0.f) << 1) | ((v3.z > 0.f) << 2) | ((v3.w > 0.f) << 3);
        int c = __popc(n0) + __popc(n1) + __popc(n2) + __popc(n3);
        // one scan per 128-col super-chunk
        int s = c;
        #pragma unroll
        for (int off = 1; off < 32; off <<= 1) {
            int t = __shfl_up_sync(0xffffffffu, s, off);
            if (lane >= off) s += t;
        }
        int pos = cnt + s - c;
        cnt += __shfl_sync(0xffffffffu, s, 31);
        if (c) {
            place_bits(n0, (jb + lane) * 4,      pos, row);
            place_bits(n1, (jb + 32 + lane) * 4, pos, row);
            place_bits(n2, (jb + 64 + lane) * 4, pos, row);
            place_bits(n3, (jb + 96 + lane) * 4, pos, row);
        }
    }
    if (lane == 0) g_deg[g][r] = cnt < MAXD ? cnt : MAXD;
}

// =====================================================================
// GEMM1 (standalone): Wh = x @ Wcat, tile 128x64, + s1/s2 epilogue.
// grid 256 x 256 threads, microtile 8x4.
// =====================================================================
__global__ void gemm1(const float* __restrict__ x,
                      const float* __restrict__ W1, const float* __restrict__ W2,
                      const float* __restrict__ a1, const float* __restrict__ a2) {
    __shared__ float As[16][132];
    __shared__ float Bs[16][64];
    int bid = blockIdx.x;
    int tid = threadIdx.x;
    int bx = bid & 31, by = bid >> 5;         // by in [0,8)
    int m0r = bx * 128, n0 = by * 64;
    int gsel = by >> 2, h = by & 3;
    const float* W  = gsel ? W2 : W1;         // [4,256,64]
    const float* av = (gsel ? a2 : a1) + h * 128;
    int tx = tid & 15, ty = tid >> 4;

    float acc[8][4] = {};
    for (int kb = 0; kb < FIN; kb += 16) {
        #pragma unroll
        for (int i = 0; i < 2; i++) {
            int e4 = i * 256 + tid;
            int m = e4 >> 2, k4 = e4 & 3;
            float4 v = *(const float4*)(x + (size_t)(m0r + m) * FIN + kb + k4 * 4);
            As[k4 * 4 + 0][m] = v.x; As[k4 * 4 + 1][m] = v.y;
            As[k4 * 4 + 2][m] = v.z; As[k4 * 4 + 3][m] = v.w;
        }
        {
            int k = tid >> 4, nf = (tid & 15) * 4;
            float4 bv = *(const float4*)(W + ((size_t)(h * FIN + kb + k)) * FHID + nf);
            *(float4*)&Bs[k][nf] = bv;
        }
        __syncthreads();
        #pragma unroll
        for (int kk = 0; kk < 16; kk++) {
            float a[8], b[4];
            #pragma unroll
            for (int r = 0; r < 8; r++) a[r] = As[kk][ty * 8 + r];
            #pragma unroll
            for (int c = 0; c < 4; c++) b[c] = Bs[kk][tx * 4 + c];
            #pragma unroll
            for (int r = 0; r < 8; r++)
                #pragma unroll
                for (int c = 0; c < 4; c++)
                    acc[r][c] += a[r] * b[c];
        }
        __syncthreads();
    }
    #pragma unroll
    for (int r = 0; r < 8; r++) {
        int m = m0r + ty * 8 + r;
        float4 v = make_float4(acc[r][0], acc[r][1], acc[r][2], acc[r][3]);
        *(float4*)&g_Wh[m][n0 + tx * 4] = v;
    }
    float a_s[4], a_d[4];
    #pragma unroll
    for (int c = 0; c < 4; c++) {
        a_s[c] = __ldg(av + tx * 4 + c);
        a_d[c] = __ldg(av + 64 + tx * 4 + c);
    }
    #pragma unroll
    for (int r = 0; r < 8; r++) {
        float s1 = 0.f, s2 = 0.f;
        #pragma unroll
        for (int c = 0; c < 4; c++) { s1 += acc[r][c] * a_s[c]; s2 += acc[r][c] * a_d[c]; }
        #pragma unroll
        for (int off = 1; off < 16; off <<= 1) {
            s1 += __shfl_xor_sync(0xffffffffu, s1, off);
            s2 += __shfl_xor_sync(0xffffffffu, s2, off);
        }
        if (tx == 0) {
            int m = m0r + ty * 8 + r;
            g_s1t[gsel][m][h] = s1;
            g_s2t[gsel][m][h] = s2;
        }
    }
}

// ---- 4-head gather chunk (attn1): broadcast (c, e0..e3), 2 edges per step ----
__device__ __forceinline__ void gat_chunk1(const float* __restrict__ tab, int lim,
                                           int cj, float4 ej,
                                           float& ax0, float& ay0, float& ax1, float& ay1,
                                           float& ax2, float& ay2, float& ax3, float& ay3) {
    int kk = 0;
    for (; kk + 2 <= lim; kk += 2) {
        int   ca  = __shfl_sync(0xffffffffu, cj, kk);
        int   cb  = __shfl_sync(0xffffffffu, cj, kk + 1);
        float ea0 = __shfl_sync(0xffffffffu, ej.x, kk);
        float ea1 = __shfl_sync(0xffffffffu, ej.y, kk);
        float ea2 = __shfl_sync(0xffffffffu, ej.z, kk);
        float ea3 = __shfl_sync(0xffffffffu, ej.w, kk);
        float eb0 = __shfl_sync(0xffffffffu, ej.x, kk + 1);
        float eb1 = __shfl_sync(0xffffffffu, ej.y, kk + 1);
        float eb2 = __shfl_sync(0xffffffffu, ej.z, kk + 1);
        float eb3 = __shfl_sync(0xffffffffu, ej.w, kk + 1);
        const float* ra = tab + (size_t)ca * 512;
        const float* rb = tab + (size_t)cb * 512;
        float2 va0 = *(const float2*)(ra);
        float2 va1 = *(const float2*)(ra + 64);
        float2 va2 = *(const float2*)(ra + 128);
        float2 va3 = *(const float2*)(ra + 192);
        float2 vb0 = *(const float2*)(rb);
        float2 vb1 = *(const float2*)(rb + 64);
        float2 vb2 = *(const float2*)(rb + 128);
        float2 vb3 = *(const float2*)(rb + 192);
        ax0 += ea0 * va0.x + eb0 * vb0.x;  ay0 += ea0 * va0.y + eb0 * vb0.y;
        ax1 += ea1 * va1.x + eb1 * vb1.x;  ay1 += ea1 * va1.y + eb1 * vb1.y;
        ax2 += ea2 * va2.x + eb2 * vb2.x;  ay2 += ea2 * va2.y + eb2 * vb2.y;
        ax3 += ea3 * va3.x + eb3 * vb3.x;  ay3 += ea3 * va3.y + eb3 * vb3.y;
    }
    if (kk < lim) {
        int   ca  = __shfl_sync(0xffffffffu, cj, kk);
        float ea0 = __shfl_sync(0xffffffffu, ej.x, kk);
        float ea1 = __shfl_sync(0xffffffffu, ej.y, kk);
        float ea2 = __shfl_sync(0xffffffffu, ej.z, kk);
        float ea3 = __shfl_sync(0xffffffffu, ej.w, kk);
        const float* ra = tab + (size_t)ca * 512;
        float2 va0 = *(const float2*)(ra);
        float2 va1 = *(const float2*)(ra + 64);
        float2 va2 = *(const float2*)(ra + 128);
        float2 va3 = *(const float2*)(ra + 192);
        ax0 += ea0 * va0.x;  ay0 += ea0 * va0.y;
        ax1 += ea1 * va1.x;  ay1 += ea1 * va1.y;
        ax2 += ea2 * va2.x;  ay2 += ea2 * va2.y;
        ax3 += ea3 * va3.x;  ay3 += ea3 * va3.y;
    }
}

// =====================================================================
// Layer-1 attention: ONE warp per (node, graph), all 4 heads together.
// grid 1024 x 256 -> 8 warps = 4 nodes x 2 graphs. No barriers.
// =====================================================================
__global__ void attn_layer1() {
    int tid  = threadIdx.x;
    int lane = tid & 31;
    int w    = tid >> 5;
    int n    = w >> 1;
    int g    = w & 1;
    int i    = blockIdx.x * 4 + n;

    int d = g_deg[g][i];
    float4 s1 = *(const float4*)&g_s1t[g][i][0];

    int c0 = 0, c1 = 0;
    float4 e0 = make_float4(0.f, 0.f, 0.f, 0.f);
    float4 e1 = make_float4(0.f, 0.f, 0.f, 0.f);
    if (lane < d) {
        c0 = g_cols[g][i][lane];
        float4 s2 = *(const float4*)&g_s2t[g][c0][0];
        e0.x = lkexp(s1.x + s2.x);  e0.y = lkexp(s1.y + s2.y);
        e0.z = lkexp(s1.z + s2.z);  e0.w = lkexp(s1.w + s2.w);
    }
    if (lane + 32 < d) {
        c1 = g_cols[g][i][lane + 32];
        float4 s2 = *(const float4*)&g_s2t[g][c1][0];
        e1.x = lkexp(s1.x + s2.x);  e1.y = lkexp(s1.y + s2.y);
        e1.z = lkexp(s1.z + s2.z);  e1.w = lkexp(s1.w + s2.w);
    }
    float sx = e0.x + e1.x, sy = e0.y + e1.y, sz = e0.z + e1.z, sw = e0.w + e1.w;
    #pragma unroll
    for (int off = 16; off; off >>= 1) {
        sx += __shfl_xor_sync(0xffffffffu, sx, off);
        sy += __shfl_xor_sync(0xffffffffu, sy, off);
        sz += __shfl_xor_sync(0xffffffffu, sz, off);
        sw += __shfl_xor_sync(0xffffffffu, sw, off);
    }
    float ix = 1.f / sx, iy = 1.f / sy, iz = 1.f / sz, iw = 1.f / sw;

    const float* tab = &g_Wh[0][g * 256 + 2 * lane];
    float ax0 = 0.f, ay0 = 0.f, ax1 = 0.f, ay1 = 0.f;
    float ax2 = 0.f, ay2 = 0.f, ax3 = 0.f, ay3 = 0.f;
    int lim0 = d < 32 ? d : 32;
    int lim1 = d - 32; lim1 = lim1 < 0 ? 0 : lim1;
    gat_chunk1(tab, lim0, c0, e0, ax0, ay0, ax1, ay1, ax2, ay2, ax3, ay3);
    gat_chunk1(tab, lim1, c1, e1, ax0, ay0, ax1, ay1, ax2, ay2, ax3, ay3);

    float* orow = &g_hcat[g][i][2 * lane];
    float2 o;
    o.x = elu1(ax0 * ix);  o.y = elu1(ay0 * ix);  *(float2*)(orow)       = o;
    o.x = elu1(ax1 * iy);  o.y = elu1(ay1 * iy);  *(float2*)(orow + 64)  = o;
    o.x = elu1(ax2 * iz);  o.y = elu1(ay2 * iz);  *(float2*)(orow + 128) = o;
    o.x = elu1(ax3 * iw);  o.y = elu1(ay3 * iw);  *(float2*)(orow + 192) = o;
}

// =====================================================================
// GEMM2 (both graphs, one launch): Wh2_g = hcat_g @ Wo_g, tile 64x64,
// + s1o/s2o epilogue.  grid (64, 2), block 256, microtile 4x4.
// =====================================================================
__global__ void gemm2f(const float* __restrict__ Wo1, const float* __restrict__ Wo2,
                       const float* __restrict__ ao1, const float* __restrict__ ao2) {
    __shared__ float As[16][68];
    __shared__ float Bs[16][64];
    int g = blockIdx.y;
    int m0r = blockIdx.x * 64;
    const float* A  = &g_hcat[g][0][0];
    const float* B  = g ? Wo2 : Wo1;
    const float* ao = g ? ao2 : ao1;
    int tid = threadIdx.x;
    int tx = tid & 15, ty = tid >> 4;

    float acc[4][4] = {};
    for (int kb = 0; kb < 256; kb += 16) {
        {
            int m = tid >> 2, k4 = tid & 3;
            float4 v = *(const float4*)(A + (size_t)(m0r + m) * 256 + kb + k4 * 4);
            As[k4 * 4 + 0][m] = v.x; As[k4 * 4 + 1][m] = v.y;
            As[k4 * 4 + 2][m] = v.z; As[k4 * 4 + 3][m] = v.w;
        }
        {
            int k = tid >> 4, nf = (tid & 15) * 4;
            float4 bv = *(const float4*)(B + (size_t)(kb + k) * 64 + nf);
            *(float4*)&Bs[k][nf] = bv;
        }
        __syncthreads();
        #pragma unroll
        for (int kk = 0; kk < 16; kk++) {
            float a[4], b[4];
            #pragma unroll
            for (int r = 0; r < 4; r++) a[r] = As[kk][ty * 4 + r];
            #pragma unroll
            for (int c = 0; c < 4; c++) b[c] = Bs[kk][tx * 4 + c];
            #pragma unroll
            for (int r = 0; r < 4; r++)
                #pragma unroll
                for (int c = 0; c < 4; c++)
                    acc[r][c] += a[r] * b[c];
        }
        __syncthreads();
    }
    #pragma unroll
    for (int r = 0; r < 4; r++) {
        int m = m0r + ty * 4 + r;
        float4 v = make_float4(acc[r][0], acc[r][1], acc[r][2], acc[r][3]);
        *(float4*)&g_Wh2[g][m][tx * 4] = v;
    }
    float a_s[4], a_d[4];
    #pragma unroll
    for (int c = 0; c < 4; c++) {
        a_s[c] = __ldg(ao + tx * 4 + c);
        a_d[c] = __ldg(ao + 64 + tx * 4 + c);
    }
    #pragma unroll
    for (int r = 0; r < 4; r++) {
        float s1 = 0.f, s2 = 0.f;
        #pragma unroll
        for (int c = 0; c < 4; c++) { s1 += acc[r][c] * a_s[c]; s2 += acc[r][c] * a_d[c]; }
        #pragma unroll
        for (int off = 1; off < 16; off <<= 1) {
            s1 += __shfl_xor_sync(0xffffffffu, s1, off);
            s2 += __shfl_xor_sync(0xffffffffu, s2, off);
        }
        if (tx == 0) {
            int m = m0r + ty * 4 + r;
            g_s1o[g][m] = s1;
            g_s2o[g][m] = s2;
        }
    }
}

// ---- scalar gather chunk (attn2), MLP=4, stride 64 floats ----
__device__ __forceinline__ void gat_chunk2(const float* __restrict__ tab, int lim,
                                           int cj, float ej, float& ax, float& ay) {
    int kk = 0;
    for (; kk + 4 <= lim; kk += 4) {
        int   c0 = __shfl_sync(0xffffffffu, cj, kk);
        int   c1 = __shfl_sync(0xffffffffu, cj, kk + 1);
        int   c2 = __shfl_sync(0xffffffffu, cj, kk + 2);
        int   c3 = __shfl_sync(0xffffffffu, cj, kk + 3);
        float e0 = __shfl_sync(0xffffffffu, ej, kk);
        float e1 = __shfl_sync(0xffffffffu, ej, kk + 1);
        float e2 = __shfl_sync(0xffffffffu, ej, kk + 2);
        float e3 = __shfl_sync(0xffffffffu, ej, kk + 3);
        float2 v0 = *(const float2*)(tab + (size_t)c0 * 64);
        float2 v1 = *(const float2*)(tab + (size_t)c1 * 64);
        float2 v2 = *(const float2*)(tab + (size_t)c2 * 64);
        float2 v3 = *(const float2*)(tab + (size_t)c3 * 64);
        ax += e0 * v0.x + e1 * v1.x + e2 * v2.x + e3 * v3.x;
        ay += e0 * v0.y + e1 * v1.y + e2 * v2.y + e3 * v3.y;
    }
    for (; kk < lim; kk++) {
        int   c = __shfl_sync(0xffffffffu, cj, kk);
        float e = __shfl_sync(0xffffffffu, ej, kk);
        float2 v = *(const float2*)(tab + (size_t)c * 64);
        ax += e * v.x;
        ay += e * v.y;
    }
}

// =====================================================================
// Layer-2 attention + ELU + semantic fusion.
// One warp per (node, graph); 256-thread block handles 4 nodes.
// Beta computed once via 16-lane shfl reduction in projection warps.
// =====================================================================
__global__ void attn2_final(const float* __restrict__ Wp1, const float* __restrict__ bp1,
                            const float* __restrict__ Wp2, float* __restrict__ out) {
    int tid  = threadIdx.x;
    int lane = tid & 31;
    int w    = tid >> 5;        // 0..7
    int n    = w >> 1;          // node slot 0..3
    int g    = w & 1;
    int i    = blockIdx.x * 4 + n;

    __shared__ float se[4][2][64];
    __shared__ float sw[4][2];

    int d = g_deg[g][i];
    float s1v = g_s1o[g][i];
    int c0 = 0, c1 = 0;
    float e0 = 0.f, e1 = 0.f;
    if (lane < d) {
        c0 = g_cols[g][i][lane];
        e0 = lkexp(s1v + g_s2o[g][c0]);
    }
    if (lane + 32 < d) {
        c1 = g_cols[g][i][lane + 32];
        e1 = lkexp(s1v + g_s2o[g][c1]);
    }
    float sum = e0 + e1;
    #pragma unroll
    for (int off = 16; off; off >>= 1) sum += __shfl_xor_sync(0xffffffffu, sum, off);
    float inv = 1.f / sum;

    const float* tab = &g_Wh2[g][0][2 * lane];
    float ax = 0.f, ay = 0.f;
    int lim0 = d < 32 ? d : 32;
    int lim1 = d - 32; lim1 = lim1 < 0 ? 0 : lim1;
    gat_chunk2(tab, lim0, c0, e0, ax, ay);
    gat_chunk2(tab, lim1, c1, e1, ax, ay);

    ax *= inv; ay *= inv;
    se[n][g][2 * lane]     = elu1(ax);
    se[n][g][2 * lane + 1] = elu1(ay);
    __syncthreads();

    // projection: 128 threads = 4 nodes x 2 g x 16 p; then 16-lane reduce -> sw
    if (tid < 128) {
        int pn = tid >> 5, pg = (tid >> 4) & 1, p = tid & 15;
        float s = __ldg(bp1 + p);
        #pragma unroll
        for (int f = 0; f < 64; f++) s += se[pn][pg][f] * __ldg(Wp1 + f * NPROJ + p);
        // fast tanh: (e^{2s}-1)/(e^{2s}+1)
        float e2x = __expf(2.f * s);
        float t = __fdividef(e2x - 1.f, e2x + 1.f);
        float wv = t * __ldg(Wp2 + p);
        wv += __shfl_xor_sync(0xffffffffu, wv, 1);
        wv += __shfl_xor_sync(0xffffffffu, wv, 2);
        wv += __shfl_xor_sync(0xffffffffu, wv, 4);
        wv += __shfl_xor_sync(0xffffffffu, wv, 8);
        if (p == 0) sw[pn][pg] = wv;
    }
    __syncthreads();

    // output: 256 threads = 4 nodes x 64 feats
    int on = tid >> 6, f = tid & 63;
    float w0 = sw[on][0], w1 = sw[on][1];
    float mm = fmaxf(w0, w1);
    float b0 = __expf(w0 - mm), b1 = __expf(w1 - mm);
    float ib = 1.f / (b0 + b1);
    int oi = blockIdx.x * 4 + on;
    out[(size_t)oi * 64 + f] = (b0 * se[on][0][f] + b1 * se[on][1][f]) * ib;
}

// ---------------- launch ----------------
extern "C" void kernel_launch(void* const* d_in, const int* in_sizes, int n_in,
                              void* d_out, int out_size) {
    const float* x    = (const float*)d_in[0];
    const float* sadj = (const float*)d_in[1];
    const float* sadj2= (const float*)d_in[2];
    const float* W1   = (const float*)d_in[3];
    const float* a1   = (const float*)d_in[4];
    const float* Wo1  = (const float*)d_in[5];
    const float* ao1  = (const float*)d_in[6];
    const float* W2   = (const float*)d_in[7];
    const float* a2   = (const float*)d_in[8];
    const float* Wo2  = (const float*)d_in[9];
    const float* ao2  = (const float*)d_in[10];
    const float* Wp1  = (const float*)d_in[11];
    const float* bp1  = (const float*)d_in[12];
    const float* Wp2  = (const float*)d_in[13];
    float* out = (float*)d_out;

    csr_build<<<1024, 256>>>(sadj, sadj2);
    gemm1<<<256, 256>>>(x, W1, W2, a1, a2);
    attn_layer1<<<1024, 256>>>();
    gemm2f<<<dim3(64, 2), 256>>>(Wo1, Wo2, ao1, ao2);
    attn2_final<<<1024, 256>>>(Wp1, bp1, Wp2, out);
}

// round 9
// speedup vs baseline: 1.2180x; 1.0518x over previous
#include <cuda_runtime.h>
#include <math.h>

#define N_NODES 4096
#define FIN     256
#define NHEAD   4
#define FHID    64
#define FFIN    64
#define NPROJ   16
#define MAXD    128

// ---------------- scratch ----------------
__device__ int   g_cols[2][N_NODES][MAXD];
__device__ int   g_deg [2][N_NODES];
__device__ float g_Wh  [N_NODES][512];      // x @ Wcat   (cols: g*256 + h*64 + f)
__device__ float g_s1t [2][N_NODES][4];     // layer-1 src logits, 4 heads packed
__device__ float g_s2t [2][N_NODES][4];     // layer-1 dst logits, 4 heads packed
__device__ float g_hcat[2][N_NODES][256];   // layer-1 outputs (head-concat)
__device__ float g_Wh2 [2][N_NODES][64];
__device__ float g_s1o [2][N_NODES];
__device__ float g_s2o [2][N_NODES];

__device__ __forceinline__ float lkexp(float z) {
    z = z >= 0.f ? z : 0.2f * z;
    return __expf(z);
}
__device__ __forceinline__ float elu1(float v) {
    return v > 0.f ? v : (__expf(v) - 1.f);
}

// =====================================================================
// CSR build (standalone, low regs, MLP=4): one warp per (graph,row).
// =====================================================================
__device__ __forceinline__ void place_bits(unsigned nb, int cb, int& pos, int* __restrict__ row) {
    while (nb) {
        int b = __ffs(nb) - 1;
        nb &= nb - 1;
        if (pos < MAXD) row[pos] = cb + b;
        pos++;
    }
}

__global__ void csr_build(const float* __restrict__ m0, const float* __restrict__ m1) {
    int tid  = threadIdx.x;
    int w    = blockIdx.x * 8 + (tid >> 5);
    int lane = tid & 31;
    int g = w >> 12, r = w & 4095;
    const float4* mask = (const float4*)((g ? m1 : m0) + (size_t)r * N_NODES);
    int* row = &g_cols[g][r][0];
    int cnt = 0;
    for (int jb = 0; jb < 1024; jb += 128) {
        float4 v0 = mask[jb + lane];
        float4 v1 = mask[jb + 32 + lane];
        float4 v2 = mask[jb + 64 + lane];
        float4 v3 = mask[jb + 96 + lane];
        unsigned n0 = (v0.x > 0.f) | ((v0.y > 0.f) << 1) | ((v0.z > 0.f) << 2) | ((v0.w > 0.f) << 3);
        unsigned n1 = (v1.x > 0.f) | ((v1.y > 0.f) << 1) | ((v1.z > 0.f) << 2) | ((v1.w > 0.f) << 3);
        unsigned n2 = (v2.x > 0.f) | ((v2.y > 0.f) << 1) | ((v2.z > 0.f) << 2) | ((v2.w > 0.f) << 3);
        unsigned n3 = (v3.x > 0.f) | ((v3.y > 0.f) << 1) | ((v3.z > 0.f) << 2) | ((v3.w > 0.f) << 3);
        int c = __popc(n0) + __popc(n1) + __popc(n2) + __popc(n3);
        int s = c;
        #pragma unroll
        for (int off = 1; off < 32; off <<= 1) {
            int t = __shfl_up_sync(0xffffffffu, s, off);
            if (lane >= off) s += t;
        }
        int pos = cnt + s - c;
        cnt += __shfl_sync(0xffffffffu, s, 31);
        if (c) {
            place_bits(n0, (jb + lane) * 4,      pos, row);
            place_bits(n1, (jb + 32 + lane) * 4, pos, row);
            place_bits(n2, (jb + 64 + lane) * 4, pos, row);
            place_bits(n3, (jb + 96 + lane) * 4, pos, row);
        }
    }
    if (lane == 0) g_deg[g][r] = cnt < MAXD ? cnt : MAXD;
}

// =====================================================================
// GEMM1: Wh = x @ Wcat, tile 64x64, double-buffered, grid (64,8).
// 256 threads, microtile 4x4. + s1/s2 epilogue.
// =====================================================================
__global__ void gemm1(const float* __restrict__ x,
                      const float* __restrict__ W1, const float* __restrict__ W2,
                      const float* __restrict__ a1, const float* __restrict__ a2) {
    __shared__ float As[2][16][68];
    __shared__ float Bs[2][16][64];
    int tid = threadIdx.x;
    int m0r = blockIdx.x * 64;
    int by  = blockIdx.y;                 // 0..7
    int gsel = by >> 2, h = by & 3;
    const float* W  = gsel ? W2 : W1;     // [4,256,64]
    const float* av = (gsel ? a2 : a1) + h * 128;
    int tx = tid & 15, ty = tid >> 4;

    int am = tid >> 2, ak4 = tid & 3;     // A loader: row am, float4 ak4
    int bk = tid >> 4, bn = (tid & 15) * 4;
    const float* Aptr  = x + (size_t)(m0r + am) * FIN;
    const float* Bbase = W + (size_t)h * FIN * FHID;

    float4 fa = *(const float4*)(Aptr + ak4 * 4);
    float4 fb = *(const float4*)(Bbase + (size_t)bk * FHID + bn);
    As[0][ak4 * 4 + 0][am] = fa.x; As[0][ak4 * 4 + 1][am] = fa.y;
    As[0][ak4 * 4 + 2][am] = fa.z; As[0][ak4 * 4 + 3][am] = fa.w;
    *(float4*)&Bs[0][bk][bn] = fb;
    __syncthreads();

    float acc[4][4] = {};
    #pragma unroll
    for (int t = 0; t < 16; t++) {
        int cur = t & 1;
        if (t < 15) {
            int kb = (t + 1) * 16;
            fa = *(const float4*)(Aptr + kb + ak4 * 4);
            fb = *(const float4*)(Bbase + (size_t)(kb + bk) * FHID + bn);
        }
        #pragma unroll
        for (int kk = 0; kk < 16; kk++) {
            float a[4], b[4];
            #pragma unroll
            for (int r = 0; r < 4; r++) a[r] = As[cur][kk][ty * 4 + r];
            #pragma unroll
            for (int c = 0; c < 4; c++) b[c] = Bs[cur][kk][tx * 4 + c];
            #pragma unroll
            for (int r = 0; r < 4; r++)
                #pragma unroll
                for (int c = 0; c < 4; c++)
                    acc[r][c] += a[r] * b[c];
        }
        if (t < 15) {
            int nxt = cur ^ 1;
            As[nxt][ak4 * 4 + 0][am] = fa.x; As[nxt][ak4 * 4 + 1][am] = fa.y;
            As[nxt][ak4 * 4 + 2][am] = fa.z; As[nxt][ak4 * 4 + 3][am] = fa.w;
            *(float4*)&Bs[nxt][bk][bn] = fb;
        }
        __syncthreads();
    }

    int n0 = by * 64;
    #pragma unroll
    for (int r = 0; r < 4; r++) {
        int m = m0r + ty * 4 + r;
        float4 v = make_float4(acc[r][0], acc[r][1], acc[r][2], acc[r][3]);
        *(float4*)&g_Wh[m][n0 + tx * 4] = v;
    }
    float a_s[4], a_d[4];
    #pragma unroll
    for (int c = 0; c < 4; c++) {
        a_s[c] = __ldg(av + tx * 4 + c);
        a_d[c] = __ldg(av + 64 + tx * 4 + c);
    }
    #pragma unroll
    for (int r = 0; r < 4; r++) {
        float s1 = 0.f, s2 = 0.f;
        #pragma unroll
        for (int c = 0; c < 4; c++) { s1 += acc[r][c] * a_s[c]; s2 += acc[r][c] * a_d[c]; }
        #pragma unroll
        for (int off = 1; off < 16; off <<= 1) {
            s1 += __shfl_xor_sync(0xffffffffu, s1, off);
            s2 += __shfl_xor_sync(0xffffffffu, s2, off);
        }
        if (tx == 0) {
            int m = m0r + ty * 4 + r;
            g_s1t[gsel][m][h] = s1;
            g_s2t[gsel][m][h] = s2;
        }
    }
}

// ---- 4-head gather chunk (attn1) ----
__device__ __forceinline__ void gat_chunk1(const float* __restrict__ tab, int lim,
                                           int cj, float4 ej,
                                           float& ax0, float& ay0, float& ax1, float& ay1,
                                           float& ax2, float& ay2, float& ax3, float& ay3) {
    int kk = 0;
    for (; kk + 2 <= lim; kk += 2) {
        int   ca  = __shfl_sync(0xffffffffu, cj, kk);
        int   cb  = __shfl_sync(0xffffffffu, cj, kk + 1);
        float ea0 = __shfl_sync(0xffffffffu, ej.x, kk);
        float ea1 = __shfl_sync(0xffffffffu, ej.y, kk);
        float ea2 = __shfl_sync(0xffffffffu, ej.z, kk);
        float ea3 = __shfl_sync(0xffffffffu, ej.w, kk);
        float eb0 = __shfl_sync(0xffffffffu, ej.x, kk + 1);
        float eb1 = __shfl_sync(0xffffffffu, ej.y, kk + 1);
        float eb2 = __shfl_sync(0xffffffffu, ej.z, kk + 1);
        float eb3 = __shfl_sync(0xffffffffu, ej.w, kk + 1);
        const float* ra = tab + (size_t)ca * 512;
        const float* rb = tab + (size_t)cb * 512;
        float2 va0 = *(const float2*)(ra);
        float2 va1 = *(const float2*)(ra + 64);
        float2 va2 = *(const float2*)(ra + 128);
        float2 va3 = *(const float2*)(ra + 192);
        float2 vb0 = *(const float2*)(rb);
        float2 vb1 = *(const float2*)(rb + 64);
        float2 vb2 = *(const float2*)(rb + 128);
        float2 vb3 = *(const float2*)(rb + 192);
        ax0 += ea0 * va0.x + eb0 * vb0.x;  ay0 += ea0 * va0.y + eb0 * vb0.y;
        ax1 += ea1 * va1.x + eb1 * vb1.x;  ay1 += ea1 * va1.y + eb1 * vb1.y;
        ax2 += ea2 * va2.x + eb2 * vb2.x;  ay2 += ea2 * va2.y + eb2 * vb2.y;
        ax3 += ea3 * va3.x + eb3 * vb3.x;  ay3 += ea3 * va3.y + eb3 * vb3.y;
    }
    if (kk < lim) {
        int   ca  = __shfl_sync(0xffffffffu, cj, kk);
        float ea0 = __shfl_sync(0xffffffffu, ej.x, kk);
        float ea1 = __shfl_sync(0xffffffffu, ej.y, kk);
        float ea2 = __shfl_sync(0xffffffffu, ej.z, kk);
        float ea3 = __shfl_sync(0xffffffffu, ej.w, kk);
        const float* ra = tab + (size_t)ca * 512;
        float2 va0 = *(const float2*)(ra);
        float2 va1 = *(const float2*)(ra + 64);
        float2 va2 = *(const float2*)(ra + 128);
        float2 va3 = *(const float2*)(ra + 192);
        ax0 += ea0 * va0.x;  ay0 += ea0 * va0.y;
        ax1 += ea1 * va1.x;  ay1 += ea1 * va1.y;
        ax2 += ea2 * va2.x;  ay2 += ea2 * va2.y;
        ax3 += ea3 * va3.x;  ay3 += ea3 * va3.y;
    }
}

// =====================================================================
// Layer-1 attention: ONE warp per (node, graph), all 4 heads together.
// =====================================================================
__global__ void attn_layer1() {
    int tid  = threadIdx.x;
    int lane = tid & 31;
    int w    = tid >> 5;
    int n    = w >> 1;
    int g    = w & 1;
    int i    = blockIdx.x * 4 + n;

    int d = g_deg[g][i];
    float4 s1 = *(const float4*)&g_s1t[g][i][0];

    int c0 = 0, c1 = 0;
    float4 e0 = make_float4(0.f, 0.f, 0.f, 0.f);
    float4 e1 = make_float4(0.f, 0.f, 0.f, 0.f);
    if (lane < d) {
        c0 = g_cols[g][i][lane];
        float4 s2 = *(const float4*)&g_s2t[g][c0][0];
        e0.x = lkexp(s1.x + s2.x);  e0.y = lkexp(s1.y + s2.y);
        e0.z = lkexp(s1.z + s2.z);  e0.w = lkexp(s1.w + s2.w);
    }
    if (lane + 32 < d) {
        c1 = g_cols[g][i][lane + 32];
        float4 s2 = *(const float4*)&g_s2t[g][c1][0];
        e1.x = lkexp(s1.x + s2.x);  e1.y = lkexp(s1.y + s2.y);
        e1.z = lkexp(s1.z + s2.z);  e1.w = lkexp(s1.w + s2.w);
    }
    float sx = e0.x + e1.x, sy = e0.y + e1.y, sz = e0.z + e1.z, sw = e0.w + e1.w;
    #pragma unroll
    for (int off = 16; off; off >>= 1) {
        sx += __shfl_xor_sync(0xffffffffu, sx, off);
        sy += __shfl_xor_sync(0xffffffffu, sy, off);
        sz += __shfl_xor_sync(0xffffffffu, sz, off);
        sw += __shfl_xor_sync(0xffffffffu, sw, off);
    }
    float ix = 1.f / sx, iy = 1.f / sy, iz = 1.f / sz, iw = 1.f / sw;

    const float* tab = &g_Wh[0][g * 256 + 2 * lane];
    float ax0 = 0.f, ay0 = 0.f, ax1 = 0.f, ay1 = 0.f;
    float ax2 = 0.f, ay2 = 0.f, ax3 = 0.f, ay3 = 0.f;
    int lim0 = d < 32 ? d : 32;
    int lim1 = d - 32; lim1 = lim1 < 0 ? 0 : lim1;
    gat_chunk1(tab, lim0, c0, e0, ax0, ay0, ax1, ay1, ax2, ay2, ax3, ay3);
    gat_chunk1(tab, lim1, c1, e1, ax0, ay0, ax1, ay1, ax2, ay2, ax3, ay3);

    float* orow = &g_hcat[g][i][2 * lane];
    float2 o;
    o.x = elu1(ax0 * ix);  o.y = elu1(ay0 * ix);  *(float2*)(orow)       = o;
    o.x = elu1(ax1 * iy);  o.y = elu1(ay1 * iy);  *(float2*)(orow + 64)  = o;
    o.x = elu1(ax2 * iz);  o.y = elu1(ay2 * iz);  *(float2*)(orow + 128) = o;
    o.x = elu1(ax3 * iw);  o.y = elu1(ay3 * iw);  *(float2*)(orow + 192) = o;
}

// =====================================================================
// GEMM2: Wh2_g = hcat_g @ Wo_g, tile 32x64, double-buffered,
// grid (128,2), 256 threads, microtile 2x4. + s1o/s2o epilogue.
// =====================================================================
__global__ void gemm2f(const float* __restrict__ Wo1, const float* __restrict__ Wo2,
                       const float* __restrict__ ao1, const float* __restrict__ ao2) {
    __shared__ float As[2][16][36];
    __shared__ float Bs[2][16][64];
    int g = blockIdx.y;
    int m0r = blockIdx.x * 32;
    const float* A  = &g_hcat[g][0][0];
    const float* B  = g ? Wo2 : Wo1;
    const float* ao = g ? ao2 : ao1;
    int tid = threadIdx.x;
    int tx = tid & 15, ty = tid >> 4;

    int am = tid >> 2, ak4 = tid & 3;       // valid for tid < 128
    int bk = tid >> 4, bn = (tid & 15) * 4;
    const float* Aptr = A + (size_t)(m0r + am) * 256;

    float4 fa = make_float4(0.f, 0.f, 0.f, 0.f);
    if (tid < 128) fa = *(const float4*)(Aptr + ak4 * 4);
    float4 fb = *(const float4*)(B + (size_t)bk * 64 + bn);
    if (tid < 128) {
        As[0][ak4 * 4 + 0][am] = fa.x; As[0][ak4 * 4 + 1][am] = fa.y;
        As[0][ak4 * 4 + 2][am] = fa.z; As[0][ak4 * 4 + 3][am] = fa.w;
    }
    *(float4*)&Bs[0][bk][bn] = fb;
    __syncthreads();

    float acc[2][4] = {};
    #pragma unroll
    for (int t = 0; t < 16; t++) {
        int cur = t & 1;
        if (t < 15) {
            int kb = (t + 1) * 16;
            if (tid < 128) fa = *(const float4*)(Aptr + kb + ak4 * 4);
            fb = *(const float4*)(B + (size_t)(kb + bk) * 64 + bn);
        }
        #pragma unroll
        for (int kk = 0; kk < 16; kk++) {
            float a[2], b[4];
            a[0] = As[cur][kk][ty * 2];
            a[1] = As[cur][kk][ty * 2 + 1];
            #pragma unroll
            for (int c = 0; c < 4; c++) b[c] = Bs[cur][kk][tx * 4 + c];
            #pragma unroll
            for (int r = 0; r < 2; r++)
                #pragma unroll
                for (int c = 0; c < 4; c++)
                    acc[r][c] += a[r] * b[c];
        }
        if (t < 15) {
            int nxt = cur ^ 1;
            if (tid < 128) {
                As[nxt][ak4 * 4 + 0][am] = fa.x; As[nxt][ak4 * 4 + 1][am] = fa.y;
                As[nxt][ak4 * 4 + 2][am] = fa.z; As[nxt][ak4 * 4 + 3][am] = fa.w;
            }
            *(float4*)&Bs[nxt][bk][bn] = fb;
        }
        __syncthreads();
    }

    #pragma unroll
    for (int r = 0; r < 2; r++) {
        int m = m0r + ty * 2 + r;
        float4 v = make_float4(acc[r][0], acc[r][1], acc[r][2], acc[r][3]);
        *(float4*)&g_Wh2[g][m][tx * 4] = v;
    }
    float a_s[4], a_d[4];
    #pragma unroll
    for (int c = 0; c < 4; c++) {
        a_s[c] = __ldg(ao + tx * 4 + c);
        a_d[c] = __ldg(ao + 64 + tx * 4 + c);
    }
    #pragma unroll
    for (int r = 0; r < 2; r++) {
        float s1 = 0.f, s2 = 0.f;
        #pragma unroll
        for (int c = 0; c < 4; c++) { s1 += acc[r][c] * a_s[c]; s2 += acc[r][c] * a_d[c]; }
        #pragma unroll
        for (int off = 1; off < 16; off <<= 1) {
            s1 += __shfl_xor_sync(0xffffffffu, s1, off);
            s2 += __shfl_xor_sync(0xffffffffu, s2, off);
        }
        if (tx == 0) {
            int m = m0r + ty * 2 + r;
            g_s1o[g][m] = s1;
            g_s2o[g][m] = s2;
        }
    }
}

// ---- scalar gather chunk (attn2), MLP=4, stride 64 floats ----
__device__ __forceinline__ void gat_chunk2(const float* __restrict__ tab, int lim,
                                           int cj, float ej, float& ax, float& ay) {
    int kk = 0;
    for (; kk + 4 <= lim; kk += 4) {
        int   c0 = __shfl_sync(0xffffffffu, cj, kk);
        int   c1 = __shfl_sync(0xffffffffu, cj, kk + 1);
        int   c2 = __shfl_sync(0xffffffffu, cj, kk + 2);
        int   c3 = __shfl_sync(0xffffffffu, cj, kk + 3);
        float e0 = __shfl_sync(0xffffffffu, ej, kk);
        float e1 = __shfl_sync(0xffffffffu, ej, kk + 1);
        float e2 = __shfl_sync(0xffffffffu, ej, kk + 2);
        float e3 = __shfl_sync(0xffffffffu, ej, kk + 3);
        float2 v0 = *(const float2*)(tab + (size_t)c0 * 64);
        float2 v1 = *(const float2*)(tab + (size_t)c1 * 64);
        float2 v2 = *(const float2*)(tab + (size_t)c2 * 64);
        float2 v3 = *(const float2*)(tab + (size_t)c3 * 64);
        ax += e0 * v0.x + e1 * v1.x + e2 * v2.x + e3 * v3.x;
        ay += e0 * v0.y + e1 * v1.y + e2 * v2.y + e3 * v3.y;
    }
    for (; kk < lim; kk++) {
        int   c = __shfl_sync(0xffffffffu, cj, kk);
        float e = __shfl_sync(0xffffffffu, ej, kk);
        float2 v = *(const float2*)(tab + (size_t)c * 64);
        ax += e * v.x;
        ay += e * v.y;
    }
}

// =====================================================================
// Layer-2 attention + ELU + semantic fusion.
// =====================================================================
__global__ void attn2_final(const float* __restrict__ Wp1, const float* __restrict__ bp1,
                            const float* __restrict__ Wp2, float* __restrict__ out) {
    int tid  = threadIdx.x;
    int lane = tid & 31;
    int w    = tid >> 5;        // 0..7
    int n    = w >> 1;          // node slot 0..3
    int g    = w & 1;
    int i    = blockIdx.x * 4 + n;

    __shared__ float se[4][2][64];
    __shared__ float sw[4][2];

    int d = g_deg[g][i];
    float s1v = g_s1o[g][i];
    int c0 = 0, c1 = 0;
    float e0 = 0.f, e1 = 0.f;
    if (lane < d) {
        c0 = g_cols[g][i][lane];
        e0 = lkexp(s1v + g_s2o[g][c0]);
    }
    if (lane + 32 < d) {
        c1 = g_cols[g][i][lane + 32];
        e1 = lkexp(s1v + g_s2o[g][c1]);
    }
    float sum = e0 + e1;
    #pragma unroll
    for (int off = 16; off; off >>= 1) sum += __shfl_xor_sync(0xffffffffu, sum, off);
    float inv = 1.f / sum;

    const float* tab = &g_Wh2[g][0][2 * lane];
    float ax = 0.f, ay = 0.f;
    int lim0 = d < 32 ? d : 32;
    int lim1 = d - 32; lim1 = lim1 < 0 ? 0 : lim1;
    gat_chunk2(tab, lim0, c0, e0, ax, ay);
    gat_chunk2(tab, lim1, c1, e1, ax, ay);

    ax *= inv; ay *= inv;
    se[n][g][2 * lane]     = elu1(ax);
    se[n][g][2 * lane + 1] = elu1(ay);
    __syncthreads();

    if (tid < 128) {
        int pn = tid >> 5, pg = (tid >> 4) & 1, p = tid & 15;
        float s = __ldg(bp1 + p);
        #pragma unroll
        for (int f = 0; f < 64; f++) s += se[pn][pg][f] * __ldg(Wp1 + f * NPROJ + p);
        float e2x = __expf(2.f * s);
        float t = __fdividef(e2x - 1.f, e2x + 1.f);
        float wv = t * __ldg(Wp2 + p);
        wv += __shfl_xor_sync(0xffffffffu, wv, 1);
        wv += __shfl_xor_sync(0xffffffffu, wv, 2);
        wv += __shfl_xor_sync(0xffffffffu, wv, 4);
        wv += __shfl_xor_sync(0xffffffffu, wv, 8);
        if (p == 0) sw[pn][pg] = wv;
    }
    __syncthreads();

    int on = tid >> 6, f = tid & 63;
    float w0 = sw[on][0], w1 = sw[on][1];
    float mm = fmaxf(w0, w1);
    float b0 = __expf(w0 - mm), b1 = __expf(w1 - mm);
    float ib = 1.f / (b0 + b1);
    int oi = blockIdx.x * 4 + on;
    out[(size_t)oi * 64 + f] = (b0 * se[on][0][f] + b1 * se[on][1][f]) * ib;
}

// ---------------- launch ----------------
extern "C" void kernel_launch(void* const* d_in, const int* in_sizes, int n_in,
                              void* d_out, int out_size) {
    const float* x    = (const float*)d_in[0];
    const float* sadj = (const float*)d_in[1];
    const float* sadj2= (const float*)d_in[2];
    const float* W1   = (const float*)d_in[3];
    const float* a1   = (const float*)d_in[4];
    const float* Wo1  = (const float*)d_in[5];
    const float* ao1  = (const float*)d_in[6];
    const float* W2   = (const float*)d_in[7];
    const float* a2   = (const float*)d_in[8];
    const float* Wo2  = (const float*)d_in[9];
    const float* ao2  = (const float*)d_in[10];
    const float* Wp1  = (const float*)d_in[11];
    const float* bp1  = (const float*)d_in[12];
    const float* Wp2  = (const float*)d_in[13];
    float* out = (float*)d_out;

    csr_build<<<1024, 256>>>(sadj, sadj2);
    gemm1<<<dim3(64, 8), 256>>>(x, W1, W2, a1, a2);
    attn_layer1<<<1024, 256>>>();
    gemm2f<<<dim3(128, 2), 256>>>(Wo1, Wo2, ao1, ao2);
    attn2_final<<<1024, 256>>>(Wp1, bp1, Wp2, out);
}